// round 1
// baseline (speedup 1.0000x reference)
#include <cuda_runtime.h>

// Problem constants (fixed by the dataset)
#define NN 512          // nodes (attention axis)
#define TT 32           // time steps
#define HH 8            // heads
#define DD 16           // per-head dim
#define CC 128          // embed
#define NP (TT*HH)      // 256 (t,h) pairs

// Scratch: per-(t,h) panels [NP][NN][DD], fp32. 4 x 8.4 MB.
__device__ float g_Q[NP*NN*DD];
__device__ float g_K[NP*NN*DD];
__device__ float g_V[NP*NN*DD];
__device__ float g_O[NP*NN*DD];

// ---------------------------------------------------------------------------
// Kernel 1: per-head projections. q,v from `values` (reference bug), k from
// `keys`. One thread per (n,t,h): 3 x 16x16 matvec, weights broadcast from smem.
// ---------------------------------------------------------------------------
__global__ __launch_bounds__(256) void proj_kernel(
    const float* __restrict__ values, const float* __restrict__ keys,
    const float* __restrict__ Wq, const float* __restrict__ Wk,
    const float* __restrict__ Wv)
{
    __shared__ float wq[256], wk[256], wv[256];
    int tid = threadIdx.x;
    wq[tid] = Wq[tid]; wk[tid] = Wk[tid]; wv[tid] = Wv[tid];
    __syncthreads();

    int idx = blockIdx.x * 256 + tid;       // (n*TT + t)*HH + h
    int h  = idx & 7;
    int nt = idx >> 3;                      // n*TT + t
    int t  = nt & 31;
    int n  = nt >> 5;

    const float4* xin = (const float4*)(values + nt*CC + h*DD);
    const float4* yin = (const float4*)(keys   + nt*CC + h*DD);
    float x[16], y[16];
    #pragma unroll
    for (int i = 0; i < 4; i++) {
        ((float4*)x)[i] = xin[i];
        ((float4*)y)[i] = yin[i];
    }

    float q[16], k[16], v[16];
    #pragma unroll
    for (int e = 0; e < 16; e++) {
        float aq = 0.f, ak = 0.f, av = 0.f;
        #pragma unroll
        for (int d = 0; d < 16; d++) {
            aq = fmaf(x[d], wq[e*16+d], aq);
            ak = fmaf(y[d], wk[e*16+d], ak);
            av = fmaf(x[d], wv[e*16+d], av);
        }
        q[e] = aq; k[e] = ak; v[e] = av;
    }

    int p = t*HH + h;
    int base = (p*NN + n) * DD;
    #pragma unroll
    for (int i = 0; i < 4; i++) {
        ((float4*)(g_Q + base))[i] = ((float4*)q)[i];
        ((float4*)(g_K + base))[i] = ((float4*)k)[i];
        ((float4*)(g_V + base))[i] = ((float4*)v)[i];
    }
}

// ---------------------------------------------------------------------------
// Kernel 2: attention over nodes, per (t,h) pair. Softmax WITHOUT max-sub
// (scores provably small), no branches. K/V streamed through 32KB smem in 2
// chunks -> 7 CTAs/SM. grid = 256 pairs x 4 q-splits, 1 thread per q row.
// ---------------------------------------------------------------------------
#define KCHUNK 256
__global__ __launch_bounds__(128) void attn_kernel()
{
    __shared__ float Ks[KCHUNK*DD];   // 16 KB
    __shared__ float Vs[KCHUNK*DD];   // 16 KB

    int p     = blockIdx.x >> 2;
    int split = blockIdx.x & 3;
    int row   = split * 128 + threadIdx.x;

    // q row, with softmax scale * log2(e) pre-folded
    const float cs = 0.08838834764831845f * 1.4426950408889634f; // 1/sqrt(128)*log2e
    float q[16];
    {
        const float4* qg = (const float4*)(g_Q + (p*NN + row)*DD);
        #pragma unroll
        for (int i = 0; i < 4; i++) ((float4*)q)[i] = qg[i];
        #pragma unroll
        for (int i = 0; i < 16; i++) q[i] *= cs;
    }

    float acc[16];
    #pragma unroll
    for (int i = 0; i < 16; i++) acc[i] = 0.f;
    float l = 0.f;

    for (int ch = 0; ch < 2; ch++) {
        const float4* Kg = (const float4*)(g_K + (p*NN + ch*KCHUNK)*DD);
        const float4* Vg = (const float4*)(g_V + (p*NN + ch*KCHUNK)*DD);
        __syncthreads();   // protect smem from previous chunk's readers
        for (int i = threadIdx.x; i < KCHUNK*DD/4; i += 128) {
            ((float4*)Ks)[i] = Kg[i];
            ((float4*)Vs)[i] = Vg[i];
        }
        __syncthreads();

        const float4* K4 = (const float4*)Ks;
        const float4* V4 = (const float4*)Vs;
        #pragma unroll 2
        for (int kk = 0; kk < KCHUNK; kk++) {
            float4 a = K4[kk*4+0], b = K4[kk*4+1], c = K4[kk*4+2], d = K4[kk*4+3];
            float s0 = fmaf(q[0],  a.x, fmaf(q[1],  a.y, fmaf(q[2],  a.z, q[3]*a.w)));
            float s1 = fmaf(q[4],  b.x, fmaf(q[5],  b.y, fmaf(q[6],  b.z, q[7]*b.w)));
            float s2 = fmaf(q[8],  c.x, fmaf(q[9],  c.y, fmaf(q[10], c.z, q[11]*c.w)));
            float s3 = fmaf(q[12], d.x, fmaf(q[13], d.y, fmaf(q[14], d.z, q[15]*d.w)));
            float s = (s0 + s1) + (s2 + s3);
            float pw;
            asm("ex2.approx.f32 %0, %1;" : "=f"(pw) : "f"(s));
            l += pw;
            float4 va = V4[kk*4+0], vb = V4[kk*4+1], vc = V4[kk*4+2], vd = V4[kk*4+3];
            acc[0]  = fmaf(pw, va.x, acc[0]);  acc[1]  = fmaf(pw, va.y, acc[1]);
            acc[2]  = fmaf(pw, va.z, acc[2]);  acc[3]  = fmaf(pw, va.w, acc[3]);
            acc[4]  = fmaf(pw, vb.x, acc[4]);  acc[5]  = fmaf(pw, vb.y, acc[5]);
            acc[6]  = fmaf(pw, vb.z, acc[6]);  acc[7]  = fmaf(pw, vb.w, acc[7]);
            acc[8]  = fmaf(pw, vc.x, acc[8]);  acc[9]  = fmaf(pw, vc.y, acc[9]);
            acc[10] = fmaf(pw, vc.z, acc[10]); acc[11] = fmaf(pw, vc.w, acc[11]);
            acc[12] = fmaf(pw, vd.x, acc[12]); acc[13] = fmaf(pw, vd.y, acc[13]);
            acc[14] = fmaf(pw, vd.z, acc[14]); acc[15] = fmaf(pw, vd.w, acc[15]);
        }
    }

    float inv = 1.0f / l;
    #pragma unroll
    for (int i = 0; i < 16; i++) acc[i] *= inv;
    float4* og = (float4*)(g_O + (p*NN + row)*DD);
    #pragma unroll
    for (int i = 0; i < 4; i++) og[i] = ((float4*)acc)[i];
}

// ---------------------------------------------------------------------------
// Kernel 3: final FC. out[n,t,e] = sum_c O[n,t,c]*Wfc[e,c] + bfc[e].
// Gathers the [t,h][n][d] panels back to row-major x[128]. Wfc in smem with
// pitch 129 (conflict-free: lane e-stride 1 -> bank step 1). 4x4 register tile.
// ---------------------------------------------------------------------------
#define FC_ROWS 32
#define FC_WPITCH 129
#define FC_SMEM ((CC*FC_WPITCH + FC_ROWS*CC) * 4)   // 82432 bytes

__global__ __launch_bounds__(256) void fc_kernel(
    const float* __restrict__ Wfc, const float* __restrict__ bfc,
    float* __restrict__ out)
{
    extern __shared__ float sh[];
    float* Wsh = sh;                    // [128][129]
    float* Xs  = sh + CC*FC_WPITCH;     // [32][128]
    int tid = threadIdx.x;

    for (int i = tid; i < CC*CC; i += 256)
        Wsh[(i >> 7)*FC_WPITCH + (i & 127)] = Wfc[i];

    int row0 = blockIdx.x * FC_ROWS;    // global row = n*TT + t
    for (int i = tid; i < FC_ROWS*CC/4; i += 256) {   // 1024 float4 gathers
        int r   = i >> 5;               // 0..31
        int c4  = i & 31;               // float4 index within the 128-col row
        int h   = c4 >> 2;
        int d4  = c4 & 3;
        int grow = row0 + r;
        int n = grow / TT, t = grow % TT;
        const float4* src = (const float4*)(g_O + ((t*HH + h)*NN + n)*DD + d4*4);
        ((float4*)(Xs + r*CC))[c4] = *src;
    }
    __syncthreads();

    int lane = tid & 31;
    int w    = tid >> 5;                // 0..7
    int r0   = w * 4;                   // 4 rows per warp
    float acc[4][4];
    #pragma unroll
    for (int r = 0; r < 4; r++)
        #pragma unroll
        for (int i = 0; i < 4; i++) acc[r][i] = 0.f;

    #pragma unroll 4
    for (int c = 0; c < CC; c++) {
        float xv[4];
        #pragma unroll
        for (int r = 0; r < 4; r++) xv[r] = Xs[(r0 + r)*CC + c];   // broadcast
        #pragma unroll
        for (int i = 0; i < 4; i++) {
            float wv = Wsh[(lane + 32*i)*FC_WPITCH + c];           // conflict-free
            #pragma unroll
            for (int r = 0; r < 4; r++) acc[r][i] = fmaf(xv[r], wv, acc[r][i]);
        }
    }

    #pragma unroll
    for (int i = 0; i < 4; i++) {
        int e = lane + 32*i;
        float b = bfc[e];
        #pragma unroll
        for (int r = 0; r < 4; r++)
            out[(row0 + r0 + r)*CC + e] = acc[r][i] + b;
    }
}

// ---------------------------------------------------------------------------
// Launch. Inputs identified by element count (robust to the scalar `heads`
// input's presence/position): 3x 2097152 = values,keys,query(in order);
// 3x 256 = Wq,Wk,Wv; 16384 = Wfc; 128 = bfc.
// ---------------------------------------------------------------------------
extern "C" void kernel_launch(void* const* d_in, const int* in_sizes, int n_in,
                              void* d_out, int out_size)
{
    const float *values = nullptr, *keys = nullptr, *query = nullptr;
    const float *Wq = nullptr, *Wk = nullptr, *Wv = nullptr;
    const float *Wfc = nullptr, *bfc = nullptr;
    for (int i = 0; i < n_in; i++) {
        int sz = in_sizes[i];
        const float* p = (const float*)d_in[i];
        if (sz == NN*TT*CC) {
            if (!values) values = p; else if (!keys) keys = p; else if (!query) query = p;
        } else if (sz == DD*DD) {
            if (!Wq) Wq = p; else if (!Wk) Wk = p; else if (!Wv) Wv = p;
        } else if (sz == CC*CC) {
            Wfc = p;
        } else if (sz == CC) {
            bfc = p;
        }
        // sz == 1 -> `heads` scalar, fixed to 8 at compile time
    }

    cudaFuncSetAttribute(fc_kernel, cudaFuncAttributeMaxDynamicSharedMemorySize, FC_SMEM);

    proj_kernel<<<(NN*TT*HH)/256, 256>>>(values, keys, Wq, Wk, Wv);
    attn_kernel<<<NP*4, 128>>>();
    fc_kernel<<<(NN*TT)/FC_ROWS, 256, FC_SMEM>>>(Wfc, bfc, (float*)d_out);
}

// round 3
// speedup vs baseline: 1.8496x; 1.8496x over previous
#include <cuda_runtime.h>
#include <cstdint>

#define NN 512          // nodes (attention axis)
#define TT 32           // time steps
#define HH 8            // heads
#define DD 16           // per-head dim
#define CC 128          // embed
#define NP (TT*HH)      // 256 (t,h) pairs

__device__ float g_Q[NP*NN*DD];
__device__ float g_K[NP*NN*DD];
__device__ float g_V[NP*NN*DD];
__device__ float g_O[NP*NN*DD];

__device__ __forceinline__ uint32_t f2tf(float f){
    uint32_t r; asm("cvt.rna.tf32.f32 %0, %1;" : "=r"(r) : "f"(f)); return r;
}
__device__ __forceinline__ float ex2f(float x){
    float r; asm("ex2.approx.f32 %0, %1;" : "=f"(r) : "f"(x)); return r;
}
__device__ __forceinline__ void mma_tf32(float& c0, float& c1, float& c2, float& c3,
                                         uint32_t a0, uint32_t a1, uint32_t a2, uint32_t a3,
                                         uint32_t b0, uint32_t b1){
    asm volatile("mma.sync.aligned.m16n8k8.row.col.f32.tf32.tf32.f32 "
                 "{%0,%1,%2,%3},{%4,%5,%6,%7},{%8,%9},{%0,%1,%2,%3};"
                 : "+f"(c0), "+f"(c1), "+f"(c2), "+f"(c3)
                 : "r"(a0), "r"(a1), "r"(a2), "r"(a3), "r"(b0), "r"(b1));
}

// ---------------------------------------------------------------------------
// Kernel 1: per-head projections. q,v from `values` (reference bug), k from
// `keys`. Weights as float4 in smem: 4 FMA per LDS.128.
// ---------------------------------------------------------------------------
__global__ __launch_bounds__(256) void proj_kernel(
    const float* __restrict__ values, const float* __restrict__ keys,
    const float* __restrict__ Wq, const float* __restrict__ Wk,
    const float* __restrict__ Wv)
{
    __shared__ float4 wq[64], wk[64], wv[64];
    int tid = threadIdx.x;
    if (tid < 64)       wq[tid]      = ((const float4*)Wq)[tid];
    else if (tid < 128) wk[tid-64]   = ((const float4*)Wk)[tid-64];
    else if (tid < 192) wv[tid-128]  = ((const float4*)Wv)[tid-128];
    __syncthreads();

    int idx = blockIdx.x * 256 + tid;       // (n*TT + t)*HH + h
    int h  = idx & 7;
    int nt = idx >> 3;
    int t  = nt & 31;
    int n  = nt >> 5;

    const float4* xin = (const float4*)(values + nt*CC + h*DD);
    const float4* yin = (const float4*)(keys   + nt*CC + h*DD);
    float4 X[4], Y[4];
    #pragma unroll
    for (int i = 0; i < 4; i++) { X[i] = xin[i]; Y[i] = yin[i]; }

    float q[16], k[16], v[16];
    #pragma unroll
    for (int e = 0; e < 16; e++) {
        float aq = 0.f, ak = 0.f, av = 0.f;
        #pragma unroll
        for (int d4 = 0; d4 < 4; d4++) {
            float4 a = wq[e*4+d4];
            aq = fmaf(X[d4].x, a.x, aq); aq = fmaf(X[d4].y, a.y, aq);
            aq = fmaf(X[d4].z, a.z, aq); aq = fmaf(X[d4].w, a.w, aq);
            float4 b = wk[e*4+d4];
            ak = fmaf(Y[d4].x, b.x, ak); ak = fmaf(Y[d4].y, b.y, ak);
            ak = fmaf(Y[d4].z, b.z, ak); ak = fmaf(Y[d4].w, b.w, ak);
            float4 c = wv[e*4+d4];
            av = fmaf(X[d4].x, c.x, av); av = fmaf(X[d4].y, c.y, av);
            av = fmaf(X[d4].z, c.z, av); av = fmaf(X[d4].w, c.w, av);
        }
        q[e] = aq; k[e] = ak; v[e] = av;
    }

    int p = t*HH + h;
    int base = (p*NN + n) * DD;
    #pragma unroll
    for (int i = 0; i < 4; i++) {
        ((float4*)(g_Q + base))[i] = ((float4*)q)[i];
        ((float4*)(g_K + base))[i] = ((float4*)k)[i];
        ((float4*)(g_V + base))[i] = ((float4*)v)[i];
    }
}

// ---------------------------------------------------------------------------
// Kernel 2: mma.sync tf32 attention. One CTA = (pair, 128 q-rows); each warp
// owns 16 q-rows and streams 64 node-tiles of 8. P stays in registers:
// S-accum fragment -> exp -> tf32 -> intra-quad shfl relayout -> A operand of
// the AV mma. Softmax without max-subtraction (|logit| small, validated R1);
// l sums the tf32-ROUNDED p values so normalization cancels rounding bias.
// Smem pitches: Kt 520 words -> B-frag bank = 8t+g (perfect); Vt 516 words ->
// bank = 4g+t (perfect); Q pitch 20 (loaded once).
// ---------------------------------------------------------------------------
#define QS_PITCH 20
#define KT_PITCH 520
#define VT_PITCH 516
#define QS_FLOATS (128*QS_PITCH)                 // 2560
#define KT_FLOATS (16*KT_PITCH)                  // 8320
#define VT_FLOATS (16*VT_PITCH)                  // 8256
#define ATTN_SMEM ((QS_FLOATS + KT_FLOATS + VT_FLOATS) * 4)   // 76544 B

__global__ __launch_bounds__(256, 2) void attn_mma_kernel()
{
    extern __shared__ float sm[];
    float* Qs = sm;                      // [128][20] tf32 (scaled)
    float* Kt = sm + QS_FLOATS;          // [16][520] tf32  Kt[d][node]
    float* Vt = Kt + KT_FLOATS;          // [16][516] tf32  Vt[d][node]

    int tid  = threadIdx.x;
    int lane = tid & 31, w = tid >> 5;
    int g  = lane >> 2;                  // quad row 0..7
    int t  = lane & 3;                   // quad col 0..3
    int p  = blockIdx.x >> 2, qb = blockIdx.x & 3;
    const float cs = 0.08838834764831845f * 1.4426950408889634f; // 1/sqrt(128)*log2e

    const float* Qg = g_Q + (p*NN + qb*128)*DD;
    const float* Kg = g_K + p*NN*DD;
    const float* Vg = g_V + p*NN*DD;

    // ---- stage Q (scaled tf32) ----
    {
        int r = tid >> 1, half = tid & 1;
        const float4* s4 = (const float4*)(Qg + r*DD + half*8);
        float4 v0 = s4[0], v1 = s4[1];
        float* dst = Qs + r*QS_PITCH + half*8;
        dst[0] = __uint_as_float(f2tf(v0.x*cs)); dst[1] = __uint_as_float(f2tf(v0.y*cs));
        dst[2] = __uint_as_float(f2tf(v0.z*cs)); dst[3] = __uint_as_float(f2tf(v0.w*cs));
        dst[4] = __uint_as_float(f2tf(v1.x*cs)); dst[5] = __uint_as_float(f2tf(v1.y*cs));
        dst[6] = __uint_as_float(f2tf(v1.z*cs)); dst[7] = __uint_as_float(f2tf(v1.w*cs));
    }
    // ---- stage Kt / Vt (transposed tf32) ----
    #pragma unroll
    for (int rr = 0; rr < 2; rr++) {
        int node = tid + rr*256;
        const float4* ks = (const float4*)(Kg + node*DD);
        const float4* vs = (const float4*)(Vg + node*DD);
        float4 a;
        a = ks[0]; Kt[ 0*KT_PITCH+node]=__uint_as_float(f2tf(a.x)); Kt[ 1*KT_PITCH+node]=__uint_as_float(f2tf(a.y));
                   Kt[ 2*KT_PITCH+node]=__uint_as_float(f2tf(a.z)); Kt[ 3*KT_PITCH+node]=__uint_as_float(f2tf(a.w));
        a = ks[1]; Kt[ 4*KT_PITCH+node]=__uint_as_float(f2tf(a.x)); Kt[ 5*KT_PITCH+node]=__uint_as_float(f2tf(a.y));
                   Kt[ 6*KT_PITCH+node]=__uint_as_float(f2tf(a.z)); Kt[ 7*KT_PITCH+node]=__uint_as_float(f2tf(a.w));
        a = ks[2]; Kt[ 8*KT_PITCH+node]=__uint_as_float(f2tf(a.x)); Kt[ 9*KT_PITCH+node]=__uint_as_float(f2tf(a.y));
                   Kt[10*KT_PITCH+node]=__uint_as_float(f2tf(a.z)); Kt[11*KT_PITCH+node]=__uint_as_float(f2tf(a.w));
        a = ks[3]; Kt[12*KT_PITCH+node]=__uint_as_float(f2tf(a.x)); Kt[13*KT_PITCH+node]=__uint_as_float(f2tf(a.y));
                   Kt[14*KT_PITCH+node]=__uint_as_float(f2tf(a.z)); Kt[15*KT_PITCH+node]=__uint_as_float(f2tf(a.w));
        a = vs[0]; Vt[ 0*VT_PITCH+node]=__uint_as_float(f2tf(a.x)); Vt[ 1*VT_PITCH+node]=__uint_as_float(f2tf(a.y));
                   Vt[ 2*VT_PITCH+node]=__uint_as_float(f2tf(a.z)); Vt[ 3*VT_PITCH+node]=__uint_as_float(f2tf(a.w));
        a = vs[1]; Vt[ 4*VT_PITCH+node]=__uint_as_float(f2tf(a.x)); Vt[ 5*VT_PITCH+node]=__uint_as_float(f2tf(a.y));
                   Vt[ 6*VT_PITCH+node]=__uint_as_float(f2tf(a.z)); Vt[ 7*VT_PITCH+node]=__uint_as_float(f2tf(a.w));
        a = vs[2]; Vt[ 8*VT_PITCH+node]=__uint_as_float(f2tf(a.x)); Vt[ 9*VT_PITCH+node]=__uint_as_float(f2tf(a.y));
                   Vt[10*VT_PITCH+node]=__uint_as_float(f2tf(a.z)); Vt[11*VT_PITCH+node]=__uint_as_float(f2tf(a.w));
        a = vs[3]; Vt[12*VT_PITCH+node]=__uint_as_float(f2tf(a.x)); Vt[13*VT_PITCH+node]=__uint_as_float(f2tf(a.y));
                   Vt[14*VT_PITCH+node]=__uint_as_float(f2tf(a.z)); Vt[15*VT_PITCH+node]=__uint_as_float(f2tf(a.w));
    }
    __syncthreads();

    // ---- Q fragments (per warp: rows w*16 .. w*16+15), 2 k-steps ----
    uint32_t qa[2][4];
    #pragma unroll
    for (int ks = 0; ks < 2; ks++) {
        const float* qr = Qs + (w*16)*QS_PITCH + ks*8;
        qa[ks][0] = __float_as_uint(qr[(g  )*QS_PITCH + t    ]);
        qa[ks][1] = __float_as_uint(qr[(g+8)*QS_PITCH + t    ]);
        qa[ks][2] = __float_as_uint(qr[(g  )*QS_PITCH + t + 4]);
        qa[ks][3] = __float_as_uint(qr[(g+8)*QS_PITCH + t + 4]);
    }

    float o00=0.f,o01=0.f,o02=0.f,o03=0.f;   // O cols 0..7
    float o10=0.f,o11=0.f,o12=0.f,o13=0.f;   // O cols 8..15
    float lg = 0.f, lg8 = 0.f;

    const int srcA = (lane & ~3) | (t >> 1);
    const int srcB = srcA + 2;
    const bool odd = (t & 1);

    const uint32_t* Ktu = (const uint32_t*)Kt;
    const uint32_t* Vtu = (const uint32_t*)Vt;

    #pragma unroll 4
    for (int tile = 0; tile < 64; tile++) {
        int n0 = tile * 8;
        // S = Q K^T  (16x8 nodes)
        float s0=0.f, s1=0.f, s2=0.f, s3=0.f;
        {
            uint32_t b0 = Ktu[( t    )*KT_PITCH + n0 + g];
            uint32_t b1 = Ktu[( t+4  )*KT_PITCH + n0 + g];
            mma_tf32(s0,s1,s2,s3, qa[0][0],qa[0][1],qa[0][2],qa[0][3], b0,b1);
            b0 = Ktu[( 8+t )*KT_PITCH + n0 + g];
            b1 = Ktu[(12+t )*KT_PITCH + n0 + g];
            mma_tf32(s0,s1,s2,s3, qa[1][0],qa[1][1],qa[1][2],qa[1][3], b0,b1);
        }
        // exp2 (scale folded into Q), round to tf32, sum rounded values
        uint32_t u0 = f2tf(ex2f(s0));
        uint32_t u1 = f2tf(ex2f(s1));
        uint32_t u2 = f2tf(ex2f(s2));
        uint32_t u3 = f2tf(ex2f(s3));
        lg  += __uint_as_float(u0) + __uint_as_float(u1);
        lg8 += __uint_as_float(u2) + __uint_as_float(u3);
        // C-layout (cols 2t,2t+1) -> A-layout (cols t,t+4), intra-quad
        uint32_t x0 = __shfl_sync(0xffffffffu, u0, srcA);
        uint32_t x1 = __shfl_sync(0xffffffffu, u1, srcA);
        uint32_t y0 = __shfl_sync(0xffffffffu, u0, srcB);
        uint32_t y1 = __shfl_sync(0xffffffffu, u1, srcB);
        uint32_t x2 = __shfl_sync(0xffffffffu, u2, srcA);
        uint32_t x3 = __shfl_sync(0xffffffffu, u3, srcA);
        uint32_t y2 = __shfl_sync(0xffffffffu, u2, srcB);
        uint32_t y3 = __shfl_sync(0xffffffffu, u3, srcB);
        uint32_t a0 = odd ? x1 : x0;
        uint32_t a2 = odd ? y1 : y0;
        uint32_t a1 = odd ? x3 : x2;
        uint32_t a3 = odd ? y3 : y2;
        // O += P * V   (k = 8 nodes of this tile)
        {
            uint32_t b0 = Vtu[( g   )*VT_PITCH + n0 + t];
            uint32_t b1 = Vtu[( g   )*VT_PITCH + n0 + t + 4];
            mma_tf32(o00,o01,o02,o03, a0,a1,a2,a3, b0,b1);
            b0 = Vtu[( 8+g )*VT_PITCH + n0 + t];
            b1 = Vtu[( 8+g )*VT_PITCH + n0 + t + 4];
            mma_tf32(o10,o11,o12,o13, a0,a1,a2,a3, b0,b1);
        }
    }

    // quad-reduce row sums (cols are spread over the 4 quad lanes)
    lg  += __shfl_xor_sync(0xffffffffu, lg,  1);
    lg  += __shfl_xor_sync(0xffffffffu, lg,  2);
    lg8 += __shfl_xor_sync(0xffffffffu, lg8, 1);
    lg8 += __shfl_xor_sync(0xffffffffu, lg8, 2);
    float invg  = 1.0f / lg;
    float invg8 = 1.0f / lg8;

    int qrow = qb*128 + w*16 + g;
    float2* d0 = (float2*)(g_O + (p*NN + qrow)*DD);
    float2* d1 = (float2*)(g_O + (p*NN + qrow + 8)*DD);
    d0[t]     = make_float2(o00*invg,  o01*invg);
    d0[4 + t] = make_float2(o10*invg,  o11*invg);
    d1[t]     = make_float2(o02*invg8, o03*invg8);
    d1[4 + t] = make_float2(o12*invg8, o13*invg8);
}

// ---------------------------------------------------------------------------
// Kernel 3: final FC (fp32, unchanged).
// ---------------------------------------------------------------------------
#define FC_ROWS 32
#define FC_WPITCH 129
#define FC_SMEM ((CC*FC_WPITCH + FC_ROWS*CC) * 4)

__global__ __launch_bounds__(256) void fc_kernel(
    const float* __restrict__ Wfc, const float* __restrict__ bfc,
    float* __restrict__ out)
{
    extern __shared__ float sh[];
    float* Wsh = sh;
    float* Xs  = sh + CC*FC_WPITCH;
    int tid = threadIdx.x;

    for (int i = tid; i < CC*CC; i += 256)
        Wsh[(i >> 7)*FC_WPITCH + (i & 127)] = Wfc[i];

    int row0 = blockIdx.x * FC_ROWS;
    for (int i = tid; i < FC_ROWS*CC/4; i += 256) {
        int r   = i >> 5;
        int c4  = i & 31;
        int h   = c4 >> 2;
        int d4  = c4 & 3;
        int grow = row0 + r;
        int n = grow / TT, t = grow % TT;
        const float4* src = (const float4*)(g_O + ((t*HH + h)*NN + n)*DD + d4*4);
        ((float4*)(Xs + r*CC))[c4] = *src;
    }
    __syncthreads();

    int lane = tid & 31;
    int w    = tid >> 5;
    int r0   = w * 4;
    float acc[4][4];
    #pragma unroll
    for (int r = 0; r < 4; r++)
        #pragma unroll
        for (int i = 0; i < 4; i++) acc[r][i] = 0.f;

    #pragma unroll 4
    for (int c = 0; c < CC; c++) {
        float xv[4];
        #pragma unroll
        for (int r = 0; r < 4; r++) xv[r] = Xs[(r0 + r)*CC + c];
        #pragma unroll
        for (int i = 0; i < 4; i++) {
            float wv = Wsh[(lane + 32*i)*FC_WPITCH + c];
            #pragma unroll
            for (int r = 0; r < 4; r++) acc[r][i] = fmaf(xv[r], wv, acc[r][i]);
        }
    }

    #pragma unroll
    for (int i = 0; i < 4; i++) {
        int e = lane + 32*i;
        float b = bfc[e];
        #pragma unroll
        for (int r = 0; r < 4; r++)
            out[(row0 + r0 + r)*CC + e] = acc[r][i] + b;
    }
}

// ---------------------------------------------------------------------------
extern "C" void kernel_launch(void* const* d_in, const int* in_sizes, int n_in,
                              void* d_out, int out_size)
{
    const float *values = nullptr, *keys = nullptr, *query = nullptr;
    const float *Wq = nullptr, *Wk = nullptr, *Wv = nullptr;
    const float *Wfc = nullptr, *bfc = nullptr;
    for (int i = 0; i < n_in; i++) {
        int sz = in_sizes[i];
        const float* p = (const float*)d_in[i];
        if (sz == NN*TT*CC) {
            if (!values) values = p; else if (!keys) keys = p; else if (!query) query = p;
        } else if (sz == DD*DD) {
            if (!Wq) Wq = p; else if (!Wk) Wk = p; else if (!Wv) Wv = p;
        } else if (sz == CC*CC) {
            Wfc = p;
        } else if (sz == CC) {
            bfc = p;
        }
    }

    cudaFuncSetAttribute(attn_mma_kernel, cudaFuncAttributeMaxDynamicSharedMemorySize, ATTN_SMEM);
    cudaFuncSetAttribute(fc_kernel, cudaFuncAttributeMaxDynamicSharedMemorySize, FC_SMEM);

    proj_kernel<<<(NN*TT*HH)/256, 256>>>(values, keys, Wq, Wk, Wv);
    attn_mma_kernel<<<NP*4, 256, ATTN_SMEM>>>();
    fc_kernel<<<(NN*TT)/FC_ROWS, 256, FC_SMEM>>>(Wfc, bfc, (float*)d_out);
}

// round 4
// speedup vs baseline: 2.0962x; 1.1333x over previous
#include <cuda_runtime.h>
#include <cstdint>

#define NN 512          // nodes (attention axis)
#define TT 32           // time steps
#define HH 8            // heads
#define DD 16           // per-head dim
#define CC 128          // embed
#define NP (TT*HH)      // 256 (t,h) pairs

__device__ float g_Q[NP*NN*DD];
__device__ float g_K[NP*NN*DD];
__device__ float g_V[NP*NN*DD];
__device__ float g_O[NP*NN*DD];

__device__ __forceinline__ uint32_t f2tf(float f){
    uint32_t r; asm("cvt.rna.tf32.f32 %0, %1;" : "=r"(r) : "f"(f)); return r;
}
__device__ __forceinline__ float ex2f(float x){
    float r; asm("ex2.approx.f32 %0, %1;" : "=f"(r) : "f"(x)); return r;
}
__device__ __forceinline__ void mma_tf32(float& c0, float& c1, float& c2, float& c3,
                                         uint32_t a0, uint32_t a1, uint32_t a2, uint32_t a3,
                                         uint32_t b0, uint32_t b1){
    asm volatile("mma.sync.aligned.m16n8k8.row.col.f32.tf32.tf32.f32 "
                 "{%0,%1,%2,%3},{%4,%5,%6,%7},{%8,%9},{%0,%1,%2,%3};"
                 : "+f"(c0), "+f"(c1), "+f"(c2), "+f"(c3)
                 : "r"(a0), "r"(a1), "r"(a2), "r"(a3), "r"(b0), "r"(b1));
}

// ---------------------------------------------------------------------------
// Kernel 1: projections, one thread = one (n,t,h) x ONE kind (q/k/v via
// grid.y). 256 FMA/thread, ~48 regs -> high occupancy. q,v read `values`
// (reference bug), k reads `keys`.
// ---------------------------------------------------------------------------
__global__ __launch_bounds__(256) void proj_kernel(
    const float* __restrict__ values, const float* __restrict__ keys,
    const float* __restrict__ Wq, const float* __restrict__ Wk,
    const float* __restrict__ Wv)
{
    int kind = blockIdx.y;
    const float* W = (kind == 0) ? Wq : (kind == 1) ? Wk : Wv;
    const float* X = (kind == 1) ? keys : values;
    float* out = (kind == 0) ? g_Q : (kind == 1) ? g_K : g_V;

    __shared__ float4 ws[64];
    int tid = threadIdx.x;
    if (tid < 64) ws[tid] = ((const float4*)W)[tid];
    __syncthreads();

    int idx = blockIdx.x * 256 + tid;       // (n*TT + t)*HH + h
    int h  = idx & 7;
    int nt = idx >> 3;
    int t  = nt & 31;
    int n  = nt >> 5;

    const float4* xin = (const float4*)(X + nt*CC + h*DD);
    float4 Xr[4];
    #pragma unroll
    for (int i = 0; i < 4; i++) Xr[i] = xin[i];

    float o[16];
    #pragma unroll
    for (int e = 0; e < 16; e++) {
        float a = 0.f;
        #pragma unroll
        for (int d4 = 0; d4 < 4; d4++) {
            float4 wv = ws[e*4 + d4];
            a = fmaf(Xr[d4].x, wv.x, a); a = fmaf(Xr[d4].y, wv.y, a);
            a = fmaf(Xr[d4].z, wv.z, a); a = fmaf(Xr[d4].w, wv.w, a);
        }
        o[e] = a;
    }

    float4* dst = (float4*)(out + ((t*HH + h)*NN + n)*DD);
    #pragma unroll
    for (int i = 0; i < 4; i++) dst[i] = ((float4*)o)[i];
}

// ---------------------------------------------------------------------------
// Kernel 2: mma.sync tf32 attention. Same structure as R3 but NO Q smem stage
// (Q fragments via 8 direct LDG.32/thread) -> smem 64.8KB -> 3 CTAs/SM.
// ---------------------------------------------------------------------------
#define KT_PITCH 520
#define VT_PITCH 516
#define KT_FLOATS (16*KT_PITCH)                  // 8320
#define VT_FLOATS (16*VT_PITCH)                  // 8256
#define ATTN_SMEM ((KT_FLOATS + VT_FLOATS) * 4)  // 66304 B

__global__ __launch_bounds__(256, 3) void attn_mma_kernel()
{
    extern __shared__ float sm[];
    float* Kt = sm;                      // [16][520] tf32  Kt[d][node]
    float* Vt = sm + KT_FLOATS;          // [16][516] tf32  Vt[d][node]

    int tid  = threadIdx.x;
    int lane = tid & 31, w = tid >> 5;
    int g  = lane >> 2;                  // quad row 0..7
    int t  = lane & 3;                   // quad col 0..3
    int p  = blockIdx.x >> 2, qb = blockIdx.x & 3;
    const float cs = 0.08838834764831845f * 1.4426950408889634f; // 1/sqrt(128)*log2e

    const float* Kg = g_K + p*NN*DD;
    const float* Vg = g_V + p*NN*DD;

    // ---- stage Kt / Vt (transposed tf32) ----
    #pragma unroll
    for (int rr = 0; rr < 2; rr++) {
        int node = tid + rr*256;
        const float4* ks = (const float4*)(Kg + node*DD);
        const float4* vs = (const float4*)(Vg + node*DD);
        float4 a;
        a = ks[0]; Kt[ 0*KT_PITCH+node]=__uint_as_float(f2tf(a.x)); Kt[ 1*KT_PITCH+node]=__uint_as_float(f2tf(a.y));
                   Kt[ 2*KT_PITCH+node]=__uint_as_float(f2tf(a.z)); Kt[ 3*KT_PITCH+node]=__uint_as_float(f2tf(a.w));
        a = ks[1]; Kt[ 4*KT_PITCH+node]=__uint_as_float(f2tf(a.x)); Kt[ 5*KT_PITCH+node]=__uint_as_float(f2tf(a.y));
                   Kt[ 6*KT_PITCH+node]=__uint_as_float(f2tf(a.z)); Kt[ 7*KT_PITCH+node]=__uint_as_float(f2tf(a.w));
        a = ks[2]; Kt[ 8*KT_PITCH+node]=__uint_as_float(f2tf(a.x)); Kt[ 9*KT_PITCH+node]=__uint_as_float(f2tf(a.y));
                   Kt[10*KT_PITCH+node]=__uint_as_float(f2tf(a.z)); Kt[11*KT_PITCH+node]=__uint_as_float(f2tf(a.w));
        a = ks[3]; Kt[12*KT_PITCH+node]=__uint_as_float(f2tf(a.x)); Kt[13*KT_PITCH+node]=__uint_as_float(f2tf(a.y));
                   Kt[14*KT_PITCH+node]=__uint_as_float(f2tf(a.z)); Kt[15*KT_PITCH+node]=__uint_as_float(f2tf(a.w));
        a = vs[0]; Vt[ 0*VT_PITCH+node]=__uint_as_float(f2tf(a.x)); Vt[ 1*VT_PITCH+node]=__uint_as_float(f2tf(a.y));
                   Vt[ 2*VT_PITCH+node]=__uint_as_float(f2tf(a.z)); Vt[ 3*VT_PITCH+node]=__uint_as_float(f2tf(a.w));
        a = vs[1]; Vt[ 4*VT_PITCH+node]=__uint_as_float(f2tf(a.x)); Vt[ 5*VT_PITCH+node]=__uint_as_float(f2tf(a.y));
                   Vt[ 6*VT_PITCH+node]=__uint_as_float(f2tf(a.z)); Vt[ 7*VT_PITCH+node]=__uint_as_float(f2tf(a.w));
        a = vs[2]; Vt[ 8*VT_PITCH+node]=__uint_as_float(f2tf(a.x)); Vt[ 9*VT_PITCH+node]=__uint_as_float(f2tf(a.y));
                   Vt[10*VT_PITCH+node]=__uint_as_float(f2tf(a.z)); Vt[11*VT_PITCH+node]=__uint_as_float(f2tf(a.w));
        a = vs[3]; Vt[12*VT_PITCH+node]=__uint_as_float(f2tf(a.x)); Vt[13*VT_PITCH+node]=__uint_as_float(f2tf(a.y));
                   Vt[14*VT_PITCH+node]=__uint_as_float(f2tf(a.z)); Vt[15*VT_PITCH+node]=__uint_as_float(f2tf(a.w));
    }

    // ---- Q fragments direct from gmem (8 LDG.32, read once per CTA) ----
    uint32_t qa[2][4];
    {
        const float* Qg = g_Q + (p*NN + qb*128 + w*16)*DD;
        int r0 = g, r1 = g + 8;
        #pragma unroll
        for (int ks = 0; ks < 2; ks++) {
            int c0 = ks*8 + t;
            qa[ks][0] = f2tf(Qg[r0*DD + c0    ] * cs);
            qa[ks][1] = f2tf(Qg[r1*DD + c0    ] * cs);
            qa[ks][2] = f2tf(Qg[r0*DD + c0 + 4] * cs);
            qa[ks][3] = f2tf(Qg[r1*DD + c0 + 4] * cs);
        }
    }
    __syncthreads();

    float o00=0.f,o01=0.f,o02=0.f,o03=0.f;
    float o10=0.f,o11=0.f,o12=0.f,o13=0.f;
    float lg = 0.f, lg8 = 0.f;

    const int srcA = (lane & ~3) | (t >> 1);
    const int srcB = srcA + 2;
    const bool odd = (t & 1);

    const uint32_t* Ktu = (const uint32_t*)Kt;
    const uint32_t* Vtu = (const uint32_t*)Vt;

    #pragma unroll 4
    for (int tile = 0; tile < 64; tile++) {
        int n0 = tile * 8;
        float s0=0.f, s1=0.f, s2=0.f, s3=0.f;
        {
            uint32_t b0 = Ktu[( t    )*KT_PITCH + n0 + g];
            uint32_t b1 = Ktu[( t+4  )*KT_PITCH + n0 + g];
            mma_tf32(s0,s1,s2,s3, qa[0][0],qa[0][1],qa[0][2],qa[0][3], b0,b1);
            b0 = Ktu[( 8+t )*KT_PITCH + n0 + g];
            b1 = Ktu[(12+t )*KT_PITCH + n0 + g];
            mma_tf32(s0,s1,s2,s3, qa[1][0],qa[1][1],qa[1][2],qa[1][3], b0,b1);
        }
        uint32_t u0 = f2tf(ex2f(s0));
        uint32_t u1 = f2tf(ex2f(s1));
        uint32_t u2 = f2tf(ex2f(s2));
        uint32_t u3 = f2tf(ex2f(s3));
        lg  += __uint_as_float(u0) + __uint_as_float(u1);
        lg8 += __uint_as_float(u2) + __uint_as_float(u3);
        uint32_t x0 = __shfl_sync(0xffffffffu, u0, srcA);
        uint32_t x1 = __shfl_sync(0xffffffffu, u1, srcA);
        uint32_t y0 = __shfl_sync(0xffffffffu, u0, srcB);
        uint32_t y1 = __shfl_sync(0xffffffffu, u1, srcB);
        uint32_t x2 = __shfl_sync(0xffffffffu, u2, srcA);
        uint32_t x3 = __shfl_sync(0xffffffffu, u3, srcA);
        uint32_t y2 = __shfl_sync(0xffffffffu, u2, srcB);
        uint32_t y3 = __shfl_sync(0xffffffffu, u3, srcB);
        uint32_t a0 = odd ? x1 : x0;
        uint32_t a2 = odd ? y1 : y0;
        uint32_t a1 = odd ? x3 : x2;
        uint32_t a3 = odd ? y3 : y2;
        {
            uint32_t b0 = Vtu[( g   )*VT_PITCH + n0 + t];
            uint32_t b1 = Vtu[( g   )*VT_PITCH + n0 + t + 4];
            mma_tf32(o00,o01,o02,o03, a0,a1,a2,a3, b0,b1);
            b0 = Vtu[( 8+g )*VT_PITCH + n0 + t];
            b1 = Vtu[( 8+g )*VT_PITCH + n0 + t + 4];
            mma_tf32(o10,o11,o12,o13, a0,a1,a2,a3, b0,b1);
        }
    }

    lg  += __shfl_xor_sync(0xffffffffu, lg,  1);
    lg  += __shfl_xor_sync(0xffffffffu, lg,  2);
    lg8 += __shfl_xor_sync(0xffffffffu, lg8, 1);
    lg8 += __shfl_xor_sync(0xffffffffu, lg8, 2);
    float invg  = 1.0f / lg;
    float invg8 = 1.0f / lg8;

    int qrow = qb*128 + w*16 + g;
    float2* d0 = (float2*)(g_O + (p*NN + qrow)*DD);
    float2* d1 = (float2*)(g_O + (p*NN + qrow + 8)*DD);
    d0[t]     = make_float2(o00*invg,  o01*invg);
    d0[4 + t] = make_float2(o10*invg,  o11*invg);
    d1[t]     = make_float2(o02*invg8, o03*invg8);
    d1[4 + t] = make_float2(o12*invg8, o13*invg8);
}

// ---------------------------------------------------------------------------
// Kernel 3: final FC via tf32 mma with A-side hi/lo split (near-fp32 on X;
// W single tf32 -> ~2.8e-4 added error). CTA = 64 rows x 128 cols; warp
// (w&3) -> 16-row group, (w>>2) -> 64-col half; 8 ntiles x 16 kk x 2 mma.
// Pitches: Xs 132 (bank = 4g+t, perfect), Ws 136 (bank = 8t+g, perfect).
// ---------------------------------------------------------------------------
#define FC_ROWS 64
#define FCX_PITCH 132
#define FCW_PITCH 136
#define FC_SMEM ((CC*FCW_PITCH + 2*FC_ROWS*FCX_PITCH + CC) * 4)  // 137728 B

__global__ __launch_bounds__(256, 1) void fc_kernel(
    const float* __restrict__ Wfc, const float* __restrict__ bfc,
    float* __restrict__ out)
{
    extern __shared__ float sh[];
    float* Ws  = sh;                             // [128 c][136] -> Ws[c][e]
    float* Xhi = Ws + CC*FCW_PITCH;              // [64 r][132]
    float* Xlo = Xhi + FC_ROWS*FCX_PITCH;        // [64 r][132]
    float* Bs  = Xlo + FC_ROWS*FCX_PITCH;        // [128]
    int tid = threadIdx.x;

    // stage W transposed as tf32: Ws[c][e] = tf32(Wfc[e][c])
    for (int i = tid; i < CC*CC; i += 256) {
        int e = i >> 7, c = i & 127;
        Ws[c*FCW_PITCH + e] = __uint_as_float(f2tf(Wfc[i]));
    }
    if (tid < CC) Bs[tid] = bfc[tid];

    // stage X rows (gather from per-(t,h) panels), split hi/lo tf32
    int row0 = blockIdx.x * FC_ROWS;
    #pragma unroll
    for (int j = 0; j < 8; j++) {
        int i   = tid + j*256;                   // 64 rows x 32 float4 = 2048
        int r   = i >> 5;
        int c4  = i & 31;
        int h   = c4 >> 2;
        int d4  = c4 & 3;
        int grow = row0 + r;
        int n = grow >> 5, t = grow & 31;
        float4 v = *(const float4*)(g_O + ((t*HH + h)*NN + n)*DD + d4*4);
        float4 hi, lo;
        hi.x = __uint_as_float(f2tf(v.x)); lo.x = __uint_as_float(f2tf(v.x - hi.x));
        hi.y = __uint_as_float(f2tf(v.y)); lo.y = __uint_as_float(f2tf(v.y - hi.y));
        hi.z = __uint_as_float(f2tf(v.z)); lo.z = __uint_as_float(f2tf(v.z - hi.z));
        hi.w = __uint_as_float(f2tf(v.w)); lo.w = __uint_as_float(f2tf(v.w - hi.w));
        ((float4*)(Xhi + r*FCX_PITCH))[c4] = hi;
        ((float4*)(Xlo + r*FCX_PITCH))[c4] = lo;
    }
    __syncthreads();

    int lane = tid & 31, w = tid >> 5;
    int g = lane >> 2, t = lane & 3;
    int rw = (w & 3) * 16;                       // row group
    int e0base = (w >> 2) * 64;                  // col half

    float acc[8][4];
    #pragma unroll
    for (int nt = 0; nt < 8; nt++)
        #pragma unroll
        for (int i = 0; i < 4; i++) acc[nt][i] = 0.f;

    const uint32_t* Xhu = (const uint32_t*)Xhi;
    const uint32_t* Xlu = (const uint32_t*)Xlo;
    const uint32_t* Wsu = (const uint32_t*)Ws;

    #pragma unroll 2
    for (int kk = 0; kk < 16; kk++) {
        int c0 = kk*8 + t;
        uint32_t ah0 = Xhu[(rw+g  )*FCX_PITCH + c0];
        uint32_t ah1 = Xhu[(rw+g+8)*FCX_PITCH + c0];
        uint32_t ah2 = Xhu[(rw+g  )*FCX_PITCH + c0 + 4];
        uint32_t ah3 = Xhu[(rw+g+8)*FCX_PITCH + c0 + 4];
        uint32_t al0 = Xlu[(rw+g  )*FCX_PITCH + c0];
        uint32_t al1 = Xlu[(rw+g+8)*FCX_PITCH + c0];
        uint32_t al2 = Xlu[(rw+g  )*FCX_PITCH + c0 + 4];
        uint32_t al3 = Xlu[(rw+g+8)*FCX_PITCH + c0 + 4];
        #pragma unroll
        for (int nt = 0; nt < 8; nt++) {
            int e0 = e0base + nt*8;
            uint32_t b0 = Wsu[(c0    )*FCW_PITCH + e0 + g];
            uint32_t b1 = Wsu[(c0 + 4)*FCW_PITCH + e0 + g];
            mma_tf32(acc[nt][0],acc[nt][1],acc[nt][2],acc[nt][3], ah0,ah1,ah2,ah3, b0,b1);
            mma_tf32(acc[nt][0],acc[nt][1],acc[nt][2],acc[nt][3], al0,al1,al2,al3, b0,b1);
        }
    }

    int gr0 = row0 + rw + g;
    #pragma unroll
    for (int nt = 0; nt < 8; nt++) {
        int e = e0base + nt*8 + 2*t;
        float b0 = Bs[e], b1 = Bs[e+1];
        *(float2*)(out + gr0*CC + e)       = make_float2(acc[nt][0] + b0, acc[nt][1] + b1);
        *(float2*)(out + (gr0+8)*CC + e)   = make_float2(acc[nt][2] + b0, acc[nt][3] + b1);
    }
}

// ---------------------------------------------------------------------------
extern "C" void kernel_launch(void* const* d_in, const int* in_sizes, int n_in,
                              void* d_out, int out_size)
{
    const float *values = nullptr, *keys = nullptr, *query = nullptr;
    const float *Wq = nullptr, *Wk = nullptr, *Wv = nullptr;
    const float *Wfc = nullptr, *bfc = nullptr;
    for (int i = 0; i < n_in; i++) {
        int sz = in_sizes[i];
        const float* p = (const float*)d_in[i];
        if (sz == NN*TT*CC) {
            if (!values) values = p; else if (!keys) keys = p; else if (!query) query = p;
        } else if (sz == DD*DD) {
            if (!Wq) Wq = p; else if (!Wk) Wk = p; else if (!Wv) Wv = p;
        } else if (sz == CC*CC) {
            Wfc = p;
        } else if (sz == CC) {
            bfc = p;
        }
    }

    cudaFuncSetAttribute(attn_mma_kernel, cudaFuncAttributeMaxDynamicSharedMemorySize, ATTN_SMEM);
    cudaFuncSetAttribute(fc_kernel, cudaFuncAttributeMaxDynamicSharedMemorySize, FC_SMEM);

    proj_kernel<<<dim3((NN*TT*HH)/256, 3), 256>>>(values, keys, Wq, Wk, Wv);
    attn_mma_kernel<<<NP*4, 256, ATTN_SMEM>>>();
    fc_kernel<<<(NN*TT)/FC_ROWS, 256, FC_SMEM>>>(Wfc, bfc, (float*)d_out);
}

// round 5
// speedup vs baseline: 2.6134x; 1.2468x over previous
#include <cuda_runtime.h>
#include <cstdint>

#define NN 512          // nodes (attention axis)
#define TT 32           // time steps
#define HH 8            // heads
#define DD 16           // per-head dim
#define CC 128          // embed

// Only surviving scratch: attention output panels [t*HH+h][n][d]
__device__ float g_O[TT*HH*NN*DD];

__device__ __forceinline__ uint32_t f2tf(float f){
    uint32_t r; asm("cvt.rna.tf32.f32 %0, %1;" : "=r"(r) : "f"(f)); return r;
}
__device__ __forceinline__ float ex2f(float x){
    float r; asm("ex2.approx.f32 %0, %1;" : "=f"(r) : "f"(x)); return r;
}
__device__ __forceinline__ void mma_tf32(float& c0, float& c1, float& c2, float& c3,
                                         uint32_t a0, uint32_t a1, uint32_t a2, uint32_t a3,
                                         uint32_t b0, uint32_t b1){
    asm volatile("mma.sync.aligned.m16n8k8.row.col.f32.tf32.tf32.f32 "
                 "{%0,%1,%2,%3},{%4,%5,%6,%7},{%8,%9},{%0,%1,%2,%3};"
                 : "+f"(c0), "+f"(c1), "+f"(c2), "+f"(c3)
                 : "r"(a0), "r"(a1), "r"(a2), "r"(a3), "r"(b0), "r"(b1));
}

// ---------------------------------------------------------------------------
// Kernel 1: FUSED proj + attention. One CTA per (t,h) pair; 256 threads.
//  - staging: each thread projects 2 nodes (q,v from `values` [reference bug],
//    k from `keys`) and writes tf32 into smem: Qs[512][20] (scaled),
//    Kt[16][520] (K^T), Vt[16][516] (V^T with in-tile column permutation
//    slot(j) = (j>>1)|((j&1)<<2)).
//  - The permutation makes exp(S) C-fragments a DIRECT A-fragment for the AV
//    mma (a = u0,u2,u1,u3): zero shuffles, zero selects in the inner loop.
//  - softmax max-free (|logit|<~2.5); l sums tf32-rounded p (bias cancels).
// ---------------------------------------------------------------------------
#define KT_PITCH 520
#define VT_PITCH 516
#define QS_PITCH 20
#define SM_KT 0
#define SM_VT (16*KT_PITCH)                       // 8320
#define SM_QS (SM_VT + 16*VT_PITCH)               // 16576
#define SM_W  (SM_QS + NN*QS_PITCH)               // 26816
#define ATTN_SMEM ((SM_W + 3*256) * 4)            // 110336 B

__global__ __launch_bounds__(256, 2) void fused_attn_kernel(
    const float* __restrict__ values, const float* __restrict__ keys,
    const float* __restrict__ Wq, const float* __restrict__ Wk,
    const float* __restrict__ Wv)
{
    extern __shared__ float sm[];
    float* Kt = sm + SM_KT;
    float* Vt = sm + SM_VT;
    float* Qs = sm + SM_QS;
    float4* wsq = (float4*)(sm + SM_W);
    float4* wsk = wsq + 64;
    float4* wsv = wsk + 64;

    int tid = threadIdx.x;
    int lane = tid & 31, w = tid >> 5;
    int g = lane >> 2, t = lane & 3;
    int p  = blockIdx.x;                 // = tq*HH + hh  (matches g_O layout)
    int hh = p & 7, tq = p >> 3;
    const float cs = 0.08838834764831845f * 1.4426950408889634f;

    if (tid < 64)       wsq[tid]     = ((const float4*)Wq)[tid];
    else if (tid < 128) wsk[tid-64]  = ((const float4*)Wk)[tid-64];
    else if (tid < 192) wsv[tid-128] = ((const float4*)Wv)[tid-128];
    __syncthreads();

    // ---- staging: project 2 nodes per thread ----
    #pragma unroll
    for (int rr = 0; rr < 2; rr++) {
        int node = tid + rr*256;
        const float4* xin = (const float4*)(values + (node*TT + tq)*CC + hh*DD);
        const float4* yin = (const float4*)(keys   + (node*TT + tq)*CC + hh*DD);
        float4 X[4], Y[4];
        #pragma unroll
        for (int i = 0; i < 4; i++) { X[i] = xin[i]; Y[i] = yin[i]; }

        int vcol = (node & ~7) | ((node >> 1) & 3) | ((node & 1) << 2);
        uint32_t qv[16];
        #pragma unroll
        for (int e = 0; e < 16; e++) {
            float aq = 0.f, ak = 0.f, av = 0.f;
            #pragma unroll
            for (int d4 = 0; d4 < 4; d4++) {
                float4 a = wsq[e*4+d4];
                aq = fmaf(X[d4].x, a.x, aq); aq = fmaf(X[d4].y, a.y, aq);
                aq = fmaf(X[d4].z, a.z, aq); aq = fmaf(X[d4].w, a.w, aq);
                float4 b = wsk[e*4+d4];
                ak = fmaf(Y[d4].x, b.x, ak); ak = fmaf(Y[d4].y, b.y, ak);
                ak = fmaf(Y[d4].z, b.z, ak); ak = fmaf(Y[d4].w, b.w, ak);
                float4 c = wsv[e*4+d4];
                av = fmaf(X[d4].x, c.x, av); av = fmaf(X[d4].y, c.y, av);
                av = fmaf(X[d4].z, c.z, av); av = fmaf(X[d4].w, c.w, av);
            }
            qv[e] = f2tf(aq * cs);
            Kt[e*KT_PITCH + node] = __uint_as_float(f2tf(ak));
            Vt[e*VT_PITCH + vcol] = __uint_as_float(f2tf(av));
        }
        float4* qdst = (float4*)(Qs + node*QS_PITCH);
        #pragma unroll
        for (int j = 0; j < 4; j++)
            qdst[j] = make_float4(__uint_as_float(qv[4*j  ]), __uint_as_float(qv[4*j+1]),
                                  __uint_as_float(qv[4*j+2]), __uint_as_float(qv[4*j+3]));
    }
    __syncthreads();

    // ---- Q fragments: warp owns rows w*64 .. w*64+63 (4 groups of 16) ----
    const uint32_t* Qu = (const uint32_t*)Qs;
    uint32_t qa[4][2][4];
    #pragma unroll
    for (int u = 0; u < 4; u++) {
        int base = w*64 + u*16;
        #pragma unroll
        for (int ks = 0; ks < 2; ks++) {
            qa[u][ks][0] = Qu[(base+g  )*QS_PITCH + ks*8 + t    ];
            qa[u][ks][1] = Qu[(base+g+8)*QS_PITCH + ks*8 + t    ];
            qa[u][ks][2] = Qu[(base+g  )*QS_PITCH + ks*8 + t + 4];
            qa[u][ks][3] = Qu[(base+g+8)*QS_PITCH + ks*8 + t + 4];
        }
    }

    float o[4][8];
    float lA[4], lB[4];
    #pragma unroll
    for (int u = 0; u < 4; u++) {
        lA[u] = 0.f; lB[u] = 0.f;
        #pragma unroll
        for (int i = 0; i < 8; i++) o[u][i] = 0.f;
    }

    const uint32_t* Ktu = (const uint32_t*)Kt;
    const uint32_t* Vtu = (const uint32_t*)Vt;

    #pragma unroll 2
    for (int tile = 0; tile < 64; tile++) {
        int n0 = tile * 8;
        uint32_t kb0 = Ktu[(t   )*KT_PITCH + n0 + g];
        uint32_t kb1 = Ktu[(t+4 )*KT_PITCH + n0 + g];
        uint32_t kb2 = Ktu[(t+8 )*KT_PITCH + n0 + g];
        uint32_t kb3 = Ktu[(t+12)*KT_PITCH + n0 + g];
        uint32_t vb0 = Vtu[(g  )*VT_PITCH + n0 + t];
        uint32_t vb1 = Vtu[(g  )*VT_PITCH + n0 + t + 4];
        uint32_t vb2 = Vtu[(g+8)*VT_PITCH + n0 + t];
        uint32_t vb3 = Vtu[(g+8)*VT_PITCH + n0 + t + 4];
        #pragma unroll
        for (int u = 0; u < 4; u++) {
            float s0=0.f, s1=0.f, s2=0.f, s3=0.f;
            mma_tf32(s0,s1,s2,s3, qa[u][0][0],qa[u][0][1],qa[u][0][2],qa[u][0][3], kb0,kb1);
            mma_tf32(s0,s1,s2,s3, qa[u][1][0],qa[u][1][1],qa[u][1][2],qa[u][1][3], kb2,kb3);
            uint32_t u0 = f2tf(ex2f(s0));
            uint32_t u1 = f2tf(ex2f(s1));
            uint32_t u2 = f2tf(ex2f(s2));
            uint32_t u3 = f2tf(ex2f(s3));
            lA[u] += __uint_as_float(u0) + __uint_as_float(u1);
            lB[u] += __uint_as_float(u2) + __uint_as_float(u3);
            // direct A-fragment thanks to Vt column permutation: (u0,u2,u1,u3)
            mma_tf32(o[u][0],o[u][1],o[u][2],o[u][3], u0,u2,u1,u3, vb0,vb1);
            mma_tf32(o[u][4],o[u][5],o[u][6],o[u][7], u0,u2,u1,u3, vb2,vb3);
        }
    }

    #pragma unroll
    for (int u = 0; u < 4; u++) {
        float la = lA[u], lb = lB[u];
        la += __shfl_xor_sync(0xffffffffu, la, 1);
        la += __shfl_xor_sync(0xffffffffu, la, 2);
        lb += __shfl_xor_sync(0xffffffffu, lb, 1);
        lb += __shfl_xor_sync(0xffffffffu, lb, 2);
        float ia = 1.0f / la, ib = 1.0f / lb;
        int qrow = w*64 + u*16 + g;
        float2* d0 = (float2*)(g_O + (p*NN + qrow)*DD);
        float2* d1 = (float2*)(g_O + (p*NN + qrow + 8)*DD);
        d0[t]     = make_float2(o[u][0]*ia, o[u][1]*ia);
        d0[4 + t] = make_float2(o[u][4]*ia, o[u][5]*ia);
        d1[t]     = make_float2(o[u][2]*ib, o[u][3]*ib);
        d1[4 + t] = make_float2(o[u][6]*ib, o[u][7]*ib);
    }
}

// ---------------------------------------------------------------------------
// Kernel 2: final FC, computed TRANSPOSED (out^T tile = W(A, natural row-major
// tf32) x X^T(B, hi/lo tf32 split)). 128 rows/CTA, 512 threads, grid=128 ->
// single wave. All smem patterns conflict-free (pitch 132: 4g+t / 4t+g).
// ---------------------------------------------------------------------------
#define FCP 132
#define FC_SMEM ((3*CC*FCP + CC) * 4)             // 203264 B

__global__ __launch_bounds__(512, 1) void fc_kernel(
    const float* __restrict__ Wfc, const float* __restrict__ bfc,
    float* __restrict__ out)
{
    extern __shared__ float sh[];
    float* Ws = sh;                // [128 e][132 c]  tf32 W (natural layout)
    float* Xh = Ws + CC*FCP;       // [128 c][132 r]  X^T hi
    float* Xl = Xh + CC*FCP;       // [128 c][132 r]  X^T lo
    float* Bs = Xl + CC*FCP;       // [128] bias
    int tid = threadIdx.x;

    // stage W as tf32 (coalesced LDG.128 -> contiguous STS.128)
    #pragma unroll
    for (int j = 0; j < 8; j++) {
        int i4 = tid + j*512;
        int e = i4 >> 5, c4 = i4 & 31;
        float4 v = ((const float4*)Wfc)[i4];
        ((float4*)(Ws + e*FCP))[c4] =
            make_float4(__uint_as_float(f2tf(v.x)), __uint_as_float(f2tf(v.y)),
                        __uint_as_float(f2tf(v.z)), __uint_as_float(f2tf(v.w)));
    }
    if (tid < CC) Bs[tid] = bfc[tid];

    // gather X rows from g_O panels; store TRANSPOSED with hi/lo split
    int row0 = blockIdx.x * 128;
    #pragma unroll
    for (int j = 0; j < 8; j++) {
        int i = tid + j*512;
        int r = i & 127, c4 = i >> 7;
        int R = row0 + r;
        int n = R >> 5, tq = R & 31;
        int h = c4 >> 2, d4 = c4 & 3;
        float4 v = *(const float4*)(g_O + ((tq*HH + h)*NN + n)*DD + d4*4);
        float hx = __uint_as_float(f2tf(v.x));
        float hy = __uint_as_float(f2tf(v.y));
        float hz = __uint_as_float(f2tf(v.z));
        float hw = __uint_as_float(f2tf(v.w));
        int c = c4*4;
        Xh[(c  )*FCP + r] = hx; Xl[(c  )*FCP + r] = __uint_as_float(f2tf(v.x - hx));
        Xh[(c+1)*FCP + r] = hy; Xl[(c+1)*FCP + r] = __uint_as_float(f2tf(v.y - hy));
        Xh[(c+2)*FCP + r] = hz; Xl[(c+2)*FCP + r] = __uint_as_float(f2tf(v.z - hz));
        Xh[(c+3)*FCP + r] = hw; Xl[(c+3)*FCP + r] = __uint_as_float(f2tf(v.w - hw));
    }
    __syncthreads();

    int lane = tid & 31, w = tid >> 5;
    int g = lane >> 2, t = lane & 3;
    int e0 = (w & 7) * 16;               // 8 e-groups of 16
    int rbase = (w >> 3) * 64;           // 2 r-halves of 64

    float acc[8][4];
    #pragma unroll
    for (int rt = 0; rt < 8; rt++)
        #pragma unroll
        for (int i = 0; i < 4; i++) acc[rt][i] = 0.f;

    const uint32_t* Wu  = (const uint32_t*)Ws;
    const uint32_t* Xhu = (const uint32_t*)Xh;
    const uint32_t* Xlu = (const uint32_t*)Xl;

    #pragma unroll 2
    for (int kk = 0; kk < 16; kk++) {
        int c0 = kk*8 + t;
        uint32_t a0 = Wu[(e0+g  )*FCP + c0    ];
        uint32_t a1 = Wu[(e0+g+8)*FCP + c0    ];
        uint32_t a2 = Wu[(e0+g  )*FCP + c0 + 4];
        uint32_t a3 = Wu[(e0+g+8)*FCP + c0 + 4];
        #pragma unroll
        for (int rt = 0; rt < 8; rt++) {
            int rb = rbase + rt*8 + g;
            uint32_t bh0 = Xhu[(c0  )*FCP + rb];
            uint32_t bh1 = Xhu[(c0+4)*FCP + rb];
            uint32_t bl0 = Xlu[(c0  )*FCP + rb];
            uint32_t bl1 = Xlu[(c0+4)*FCP + rb];
            mma_tf32(acc[rt][0],acc[rt][1],acc[rt][2],acc[rt][3], a0,a1,a2,a3, bh0,bh1);
            mma_tf32(acc[rt][0],acc[rt][1],acc[rt][2],acc[rt][3], a0,a1,a2,a3, bl0,bl1);
        }
    }

    float bg  = Bs[e0 + g];
    float bg8 = Bs[e0 + g + 8];
    #pragma unroll
    for (int rt = 0; rt < 8; rt++) {
        int R0 = row0 + rbase + rt*8 + 2*t;
        out[(R0  )*CC + e0 + g    ] = acc[rt][0] + bg;
        out[(R0+1)*CC + e0 + g    ] = acc[rt][1] + bg;
        out[(R0  )*CC + e0 + g + 8] = acc[rt][2] + bg8;
        out[(R0+1)*CC + e0 + g + 8] = acc[rt][3] + bg8;
    }
}

// ---------------------------------------------------------------------------
extern "C" void kernel_launch(void* const* d_in, const int* in_sizes, int n_in,
                              void* d_out, int out_size)
{
    const float *values = nullptr, *keys = nullptr, *query = nullptr;
    const float *Wq = nullptr, *Wk = nullptr, *Wv = nullptr;
    const float *Wfc = nullptr, *bfc = nullptr;
    for (int i = 0; i < n_in; i++) {
        int sz = in_sizes[i];
        const float* p = (const float*)d_in[i];
        if (sz == NN*TT*CC) {
            if (!values) values = p; else if (!keys) keys = p; else if (!query) query = p;
        } else if (sz == DD*DD) {
            if (!Wq) Wq = p; else if (!Wk) Wk = p; else if (!Wv) Wv = p;
        } else if (sz == CC*CC) {
            Wfc = p;
        } else if (sz == CC) {
            bfc = p;
        }
    }

    cudaFuncSetAttribute(fused_attn_kernel, cudaFuncAttributeMaxDynamicSharedMemorySize, ATTN_SMEM);
    cudaFuncSetAttribute(fc_kernel, cudaFuncAttributeMaxDynamicSharedMemorySize, FC_SMEM);

    fused_attn_kernel<<<TT*HH, 256, ATTN_SMEM>>>(values, keys, Wq, Wk, Wv);
    fc_kernel<<<(NN*TT)/128, 512, FC_SMEM>>>(Wfc, bfc, (float*)d_out);
}

// round 7
// speedup vs baseline: 3.7614x; 1.4393x over previous
#include <cuda_runtime.h>
#include <cuda_fp16.h>
#include <cstdint>

#define NN 512          // nodes (attention axis)
#define TT 32           // time steps
#define HH 8            // heads
#define DD 16           // per-head dim
#define CC 128          // embed

// Attention output: [node][t][h][dpair] as half2-in-u32, row-major = [row R][64]
__device__ uint32_t g_O16[NN*TT*HH*8];

__device__ __forceinline__ uint32_t packh2(float lo, float hi){
    uint32_t r; asm("cvt.rn.f16x2.f32 %0, %1, %2;" : "=r"(r) : "f"(hi), "f"(lo)); return r;
}
__device__ __forceinline__ uint32_t ex2h2(uint32_t x){
    uint32_t r; asm("ex2.approx.f16x2 %0, %1;" : "=r"(r) : "r"(x)); return r;
}
__device__ __forceinline__ void mma_f16(float& c0, float& c1, float& c2, float& c3,
                                        uint32_t a0, uint32_t a1, uint32_t a2, uint32_t a3,
                                        uint32_t b0, uint32_t b1){
    asm volatile("mma.sync.aligned.m16n8k16.row.col.f32.f16.f16.f32 "
                 "{%0,%1,%2,%3},{%4,%5,%6,%7},{%8,%9},{%0,%1,%2,%3};"
                 : "+f"(c0), "+f"(c1), "+f"(c2), "+f"(c3)
                 : "r"(a0), "r"(a1), "r"(a2), "r"(a3), "r"(b0), "r"(b1));
}

// ---------------------------------------------------------------------------
// Kernel 1: FUSED proj + attention, fp16 m16n8k16.
// CTA = one (t,h) pair, 256 threads, each warp owns 64 q-rows (4 groups of 16).
//  - staging: thread projects nodes tid, tid+256 (q,v from `values` [ref bug],
//    k from `keys`); packs fp16: Qs[node][dpair], Kth[dpair][node],
//    Vth[d][node] (scalar half; node-pairs read as aligned u32).
//  - S-mma C-frag == AV A-frag layout: pack(exp) feeds AV directly, no shfl.
//  - l via a third mma against ones (exact fp32 sum of fp16 p's, bias cancels).
//  - O written as half2 dpairs to g_O16 row-major for coalesced fc staging.
// ---------------------------------------------------------------------------
#define QSP 12
#define KTP 520
#define VTPW 264
#define SM_QS 0
#define SM_KT (512*QSP)                   // u32 index
#define SM_VT (SM_KT + 8*KTP)
#define SM_W  (SM_VT + 16*VTPW)
#define ATTN_SMEM ((SM_W + 3*256) * 4)    // 61184 B

__global__ __launch_bounds__(256, 2) void fused_attn_kernel(
    const float* __restrict__ values, const float* __restrict__ keys,
    const float* __restrict__ Wq, const float* __restrict__ Wk,
    const float* __restrict__ Wv)
{
    extern __shared__ uint32_t smu[];
    uint32_t* Qs  = smu + SM_QS;          // [512][12] half2
    uint32_t* Kth = smu + SM_KT;          // [8][520]  half2 (d-pairs)
    __half*   Vth = (__half*)(smu + SM_VT); // [16][528] half
    float4* wsq = (float4*)(smu + SM_W);
    float4* wsk = wsq + 64;
    float4* wsv = wsk + 64;

    int tid = threadIdx.x;
    int lane = tid & 31, w = tid >> 5;
    int g = lane >> 2, t = lane & 3;
    int p  = blockIdx.x;
    int hh = p & 7, tq = p >> 3;
    const float cs = 0.08838834764831845f * 1.4426950408889634f; // 1/sqrt(128)*log2e

    if (tid < 64)       wsq[tid]     = ((const float4*)Wq)[tid];
    else if (tid < 128) wsk[tid-64]  = ((const float4*)Wk)[tid-64];
    else if (tid < 192) wsv[tid-128] = ((const float4*)Wv)[tid-128];
    __syncthreads();

    // ---- staging: project 2 nodes/thread, pack fp16 ----
    #pragma unroll
    for (int rr = 0; rr < 2; rr++) {
        int node = tid + rr*256;
        const float4* xin = (const float4*)(values + (node*TT + tq)*CC + hh*DD);
        const float4* yin = (const float4*)(keys   + (node*TT + tq)*CC + hh*DD);
        float4 X[4], Y[4];
        #pragma unroll
        for (int i = 0; i < 4; i++) { X[i] = xin[i]; Y[i] = yin[i]; }
        #pragma unroll
        for (int dp = 0; dp < 8; dp++) {
            float aq0=0.f, ak0=0.f, av0=0.f, aq1=0.f, ak1=0.f, av1=0.f;
            #pragma unroll
            for (int d4 = 0; d4 < 4; d4++) {
                float4 a0 = wsq[(2*dp  )*4 + d4], a1 = wsq[(2*dp+1)*4 + d4];
                aq0 = fmaf(X[d4].x,a0.x,aq0); aq0 = fmaf(X[d4].y,a0.y,aq0);
                aq0 = fmaf(X[d4].z,a0.z,aq0); aq0 = fmaf(X[d4].w,a0.w,aq0);
                aq1 = fmaf(X[d4].x,a1.x,aq1); aq1 = fmaf(X[d4].y,a1.y,aq1);
                aq1 = fmaf(X[d4].z,a1.z,aq1); aq1 = fmaf(X[d4].w,a1.w,aq1);
                float4 b0 = wsk[(2*dp  )*4 + d4], b1 = wsk[(2*dp+1)*4 + d4];
                ak0 = fmaf(Y[d4].x,b0.x,ak0); ak0 = fmaf(Y[d4].y,b0.y,ak0);
                ak0 = fmaf(Y[d4].z,b0.z,ak0); ak0 = fmaf(Y[d4].w,b0.w,ak0);
                ak1 = fmaf(Y[d4].x,b1.x,ak1); ak1 = fmaf(Y[d4].y,b1.y,ak1);
                ak1 = fmaf(Y[d4].z,b1.z,ak1); ak1 = fmaf(Y[d4].w,b1.w,ak1);
                float4 c0 = wsv[(2*dp  )*4 + d4], c1 = wsv[(2*dp+1)*4 + d4];
                av0 = fmaf(X[d4].x,c0.x,av0); av0 = fmaf(X[d4].y,c0.y,av0);
                av0 = fmaf(X[d4].z,c0.z,av0); av0 = fmaf(X[d4].w,c0.w,av0);
                av1 = fmaf(X[d4].x,c1.x,av1); av1 = fmaf(X[d4].y,c1.y,av1);
                av1 = fmaf(X[d4].z,c1.z,av1); av1 = fmaf(X[d4].w,c1.w,av1);
            }
            Qs[node*QSP + dp]   = packh2(aq0*cs, aq1*cs);
            Kth[dp*KTP + node]  = packh2(ak0, ak1);
            Vth[(2*dp  )*528 + node] = __float2half_rn(av0);
            Vth[(2*dp+1)*528 + node] = __float2half_rn(av1);
        }
    }
    __syncthreads();

    // ---- Q fragments: warp rows w*64 .. +63 ----
    uint32_t qa[4][4];
    #pragma unroll
    for (int u = 0; u < 4; u++) {
        int base = w*64 + u*16;
        qa[u][0] = Qs[(base+g  )*QSP + t];
        qa[u][1] = Qs[(base+g+8)*QSP + t];
        qa[u][2] = Qs[(base+g  )*QSP + t + 4];
        qa[u][3] = Qs[(base+g+8)*QSP + t + 4];
    }

    float o[4][8], lc[4][4];
    #pragma unroll
    for (int u = 0; u < 4; u++) {
        #pragma unroll
        for (int i = 0; i < 8; i++) o[u][i] = 0.f;
        #pragma unroll
        for (int i = 0; i < 4; i++) lc[u][i] = 0.f;
    }

    const uint32_t* Vw = (const uint32_t*)Vth;
    const uint32_t ONES = 0x3C003C00u;

    #pragma unroll 2
    for (int tile = 0; tile < 32; tile++) {
        int n0 = tile*16, np0 = tile*8;
        uint32_t kb0 = Kth[(t  )*KTP + n0 + g];
        uint32_t kb1 = Kth[(t+4)*KTP + n0 + g];
        uint32_t kb2 = Kth[(t  )*KTP + n0 + 8 + g];
        uint32_t kb3 = Kth[(t+4)*KTP + n0 + 8 + g];
        uint32_t vb0 = Vw[(g  )*VTPW + np0 + t];
        uint32_t vb1 = Vw[(g  )*VTPW + np0 + t + 4];
        uint32_t vb2 = Vw[(g+8)*VTPW + np0 + t];
        uint32_t vb3 = Vw[(g+8)*VTPW + np0 + t + 4];
        #pragma unroll
        for (int u = 0; u < 4; u++) {
            float f0=0.f,f1=0.f,f2=0.f,f3=0.f;
            float h0=0.f,h1=0.f,h2=0.f,h3=0.f;
            mma_f16(f0,f1,f2,f3, qa[u][0],qa[u][1],qa[u][2],qa[u][3], kb0,kb1);
            mma_f16(h0,h1,h2,h3, qa[u][0],qa[u][1],qa[u][2],qa[u][3], kb2,kb3);
            uint32_t pa0 = ex2h2(packh2(f0,f1));   // row g,   k-nodes 2t,2t+1
            uint32_t pa1 = ex2h2(packh2(f2,f3));   // row g+8
            uint32_t pa2 = ex2h2(packh2(h0,h1));   // row g,   k-nodes 2t+8,..
            uint32_t pa3 = ex2h2(packh2(h2,h3));   // row g+8
            mma_f16(o[u][0],o[u][1],o[u][2],o[u][3], pa0,pa1,pa2,pa3, vb0,vb1);
            mma_f16(o[u][4],o[u][5],o[u][6],o[u][7], pa0,pa1,pa2,pa3, vb2,vb3);
            mma_f16(lc[u][0],lc[u][1],lc[u][2],lc[u][3], pa0,pa1,pa2,pa3, ONES,ONES);
        }
    }

    // ---- epilogue: normalize, pack half2, store row-major g_O16 ----
    #pragma unroll
    for (int u = 0; u < 4; u++) {
        float ia = 1.0f / lc[u][0];     // row g sum (quad lanes identical)
        float ib = 1.0f / lc[u][2];     // row g+8
        int node = w*64 + u*16 + g;
        uint32_t* d0 = g_O16 + (node*TT + tq)*(HH*8) + hh*8;
        uint32_t* d1 = d0 + 8*TT*(HH*8);   // node+8  (FIXED: row stride = HH*8 u32)
        d0[t]   = packh2(o[u][0]*ia, o[u][1]*ia);
        d0[t+4] = packh2(o[u][4]*ia, o[u][5]*ia);
        d1[t]   = packh2(o[u][2]*ib, o[u][3]*ib);
        d1[t+4] = packh2(o[u][6]*ib, o[u][7]*ib);
    }
}

// ---------------------------------------------------------------------------
// Kernel 2: final FC, fp16 mma. out = X @ Wfc^T + b, X from g_O16 (coalesced).
// W: hi/lo fp16 split (W-side error ~0). Per-CTA W transpose via smem bounce.
// ---------------------------------------------------------------------------
#define FCW32P 132
#define FCWHP 136
#define FCXP 72
#define FC_OFF_W32 0
#define FC_OFF_WH (CC*FCW32P)                 // floats
#define FC_OFF_WL (FC_OFF_WH + 64*FCWHP)
#define FC_OFF_X  (FC_OFF_WL + 64*FCWHP)
#define FC_OFF_B  (FC_OFF_X + 32*FCXP)
#define FC_SMEM ((FC_OFF_B + CC) * 4)         // 145920 B

__global__ __launch_bounds__(256, 1) void fc_kernel(
    const float* __restrict__ Wfc, const float* __restrict__ bfc,
    float* __restrict__ out)
{
    extern __shared__ float sh[];
    float*    Ws32 = sh + FC_OFF_W32;          // [128 e][132 c] fp32
    uint32_t* Wh   = (uint32_t*)(sh + FC_OFF_WH); // [64 cp][136 e] half2 hi
    uint32_t* Wl   = (uint32_t*)(sh + FC_OFF_WL); // [64 cp][136 e] half2 lo
    uint32_t* X16  = (uint32_t*)(sh + FC_OFF_X);  // [32 r][72 dpair] half2
    float*    Bs   = sh + FC_OFF_B;
    int tid = threadIdx.x;
    int lane = tid & 31, w = tid >> 5;
    int g = lane >> 2, t = lane & 3;
    int row0 = blockIdx.x * 32;

    // stage 1: W fp32 (coalesced), X16 (coalesced), bias
    #pragma unroll
    for (int j = 0; j < 16; j++) {
        int i4 = tid + j*256;
        int e = i4 >> 5, c4 = i4 & 31;
        ((float4*)(Ws32 + e*FCW32P))[c4] = ((const float4*)Wfc)[i4];
    }
    #pragma unroll
    for (int j = 0; j < 8; j++) {
        int i = tid + j*256;
        int r = i >> 6, c = i & 63;
        X16[r*FCXP + c] = g_O16[(row0 + r)*64 + c];
    }
    if (tid < CC) Bs[tid] = bfc[tid];
    __syncthreads();

    // stage 2: transpose + hi/lo fp16 split of W
    #pragma unroll
    for (int j = 0; j < 32; j++) {
        int i = tid + j*256;
        int cp = i >> 7, e = i & 127;
        float2 v = *(const float2*)(Ws32 + e*FCW32P + 2*cp);
        uint32_t hi = packh2(v.x, v.y);
        float hx = __half2float(((__half2*)&hi)->x);
        float hy = __half2float(((__half2*)&hi)->y);
        Wh[cp*FCWHP + e] = hi;
        Wl[cp*FCWHP + e] = packh2(v.x - hx, v.y - hy);
    }
    __syncthreads();

    // mma: warp -> (rowgroup w&1 of 16 rows, e-quarter w>>1 of 32 cols)
    int rg = (w & 1) * 16, eq = (w >> 1) * 32;
    float acc[4][4];
    #pragma unroll
    for (int nt = 0; nt < 4; nt++)
        #pragma unroll
        for (int i = 0; i < 4; i++) acc[nt][i] = 0.f;

    #pragma unroll
    for (int kk = 0; kk < 8; kk++) {
        uint32_t a0 = X16[(rg+g  )*FCXP + kk*8 + t];
        uint32_t a1 = X16[(rg+g+8)*FCXP + kk*8 + t];
        uint32_t a2 = X16[(rg+g  )*FCXP + kk*8 + t + 4];
        uint32_t a3 = X16[(rg+g+8)*FCXP + kk*8 + t + 4];
        #pragma unroll
        for (int nt = 0; nt < 4; nt++) {
            int e0 = eq + nt*8;
            uint32_t bh0 = Wh[(kk*8+t  )*FCWHP + e0 + g];
            uint32_t bh1 = Wh[(kk*8+t+4)*FCWHP + e0 + g];
            uint32_t bl0 = Wl[(kk*8+t  )*FCWHP + e0 + g];
            uint32_t bl1 = Wl[(kk*8+t+4)*FCWHP + e0 + g];
            mma_f16(acc[nt][0],acc[nt][1],acc[nt][2],acc[nt][3], a0,a1,a2,a3, bh0,bh1);
            mma_f16(acc[nt][0],acc[nt][1],acc[nt][2],acc[nt][3], a0,a1,a2,a3, bl0,bl1);
        }
    }

    #pragma unroll
    for (int nt = 0; nt < 4; nt++) {
        int e = eq + nt*8 + 2*t;
        float b0 = Bs[e], b1 = Bs[e+1];
        int R = row0 + rg + g;
        *(float2*)(out + R*CC + e)     = make_float2(acc[nt][0] + b0, acc[nt][1] + b1);
        *(float2*)(out + (R+8)*CC + e) = make_float2(acc[nt][2] + b0, acc[nt][3] + b1);
    }
}

// ---------------------------------------------------------------------------
extern "C" void kernel_launch(void* const* d_in, const int* in_sizes, int n_in,
                              void* d_out, int out_size)
{
    const float *values = nullptr, *keys = nullptr, *query = nullptr;
    const float *Wq = nullptr, *Wk = nullptr, *Wv = nullptr;
    const float *Wfc = nullptr, *bfc = nullptr;
    for (int i = 0; i < n_in; i++) {
        int sz = in_sizes[i];
        const float* ptr = (const float*)d_in[i];
        if (sz == NN*TT*CC) {
            if (!values) values = ptr; else if (!keys) keys = ptr; else if (!query) query = ptr;
        } else if (sz == DD*DD) {
            if (!Wq) Wq = ptr; else if (!Wk) Wk = ptr; else if (!Wv) Wv = ptr;
        } else if (sz == CC*CC) {
            Wfc = ptr;
        } else if (sz == CC) {
            bfc = ptr;
        }
    }

    cudaFuncSetAttribute(fused_attn_kernel, cudaFuncAttributeMaxDynamicSharedMemorySize, ATTN_SMEM);
    cudaFuncSetAttribute(fc_kernel, cudaFuncAttributeMaxDynamicSharedMemorySize, FC_SMEM);

    fused_attn_kernel<<<TT*HH, 256, ATTN_SMEM>>>(values, keys, Wq, Wk, Wv);
    fc_kernel<<<(NN*TT)/32, 256, FC_SMEM>>>(Wfc, bfc, (float*)d_out);
}

// round 8
// speedup vs baseline: 4.1152x; 1.0941x over previous
#include <cuda_runtime.h>
#include <cuda_fp16.h>
#include <cstdint>

#define NN 512          // nodes (attention axis)
#define TT 32           // time steps
#define HH 8            // heads
#define DD 16           // per-head dim
#define CC 128          // embed

// Attention output: [node][t][h][dpair] as half2-in-u32, row-major = [row R][64]
__device__ uint32_t g_O16[NN*TT*HH*8];
// Pre-converted FC weights, B-operand layout [cpair 64][e 128], hi/lo fp16 split
__device__ uint32_t g_Wh[64*CC];
__device__ uint32_t g_Wl[64*CC];

__device__ __forceinline__ uint32_t packh2(float lo, float hi){
    uint32_t r; asm("cvt.rn.f16x2.f32 %0, %1, %2;" : "=r"(r) : "f"(hi), "f"(lo)); return r;
}
__device__ __forceinline__ uint32_t ex2h2(uint32_t x){
    uint32_t r; asm("ex2.approx.f16x2 %0, %1;" : "=r"(r) : "r"(x)); return r;
}
__device__ __forceinline__ void mma_f16(float& c0, float& c1, float& c2, float& c3,
                                        uint32_t a0, uint32_t a1, uint32_t a2, uint32_t a3,
                                        uint32_t b0, uint32_t b1){
    asm volatile("mma.sync.aligned.m16n8k16.row.col.f32.f16.f16.f32 "
                 "{%0,%1,%2,%3},{%4,%5,%6,%7},{%8,%9},{%0,%1,%2,%3};"
                 : "+f"(c0), "+f"(c1), "+f"(c2), "+f"(c3)
                 : "r"(a0), "r"(a1), "r"(a2), "r"(a3), "r"(b0), "r"(b1));
}

// ---------------------------------------------------------------------------
// Kernel 0: one-shot W conversion. Wfc[e][c] fp32 -> (hi,lo) fp16 pairs in
// B-operand layout [cp][e]. 8192 threads total, runs once (~1us).
// ---------------------------------------------------------------------------
__global__ __launch_bounds__(256) void w16_prep(const float* __restrict__ Wfc)
{
    int i = blockIdx.x * 256 + threadIdx.x;   // 0..8191
    int cp = i >> 7, e = i & 127;
    float x = Wfc[e*CC + 2*cp];
    float y = Wfc[e*CC + 2*cp + 1];
    uint32_t hi = packh2(x, y);
    float hx = __half2float(((__half2*)&hi)->x);
    float hy = __half2float(((__half2*)&hi)->y);
    g_Wh[i] = hi;
    g_Wl[i] = packh2(x - hx, y - hy);
}

// ---------------------------------------------------------------------------
// Kernel 1: FUSED proj + attention, fp16 m16n8k16 (unchanged from R7 pass).
// ---------------------------------------------------------------------------
#define QSP 12
#define KTP 520
#define VTPW 264
#define SM_QS 0
#define SM_KT (512*QSP)                   // u32 index
#define SM_VT (SM_KT + 8*KTP)
#define SM_W  (SM_VT + 16*VTPW)
#define ATTN_SMEM ((SM_W + 3*256) * 4)    // 61184 B

__global__ __launch_bounds__(256, 2) void fused_attn_kernel(
    const float* __restrict__ values, const float* __restrict__ keys,
    const float* __restrict__ Wq, const float* __restrict__ Wk,
    const float* __restrict__ Wv)
{
    extern __shared__ uint32_t smu[];
    uint32_t* Qs  = smu + SM_QS;          // [512][12] half2
    uint32_t* Kth = smu + SM_KT;          // [8][520]  half2 (d-pairs)
    __half*   Vth = (__half*)(smu + SM_VT); // [16][528] half
    float4* wsq = (float4*)(smu + SM_W);
    float4* wsk = wsq + 64;
    float4* wsv = wsk + 64;

    int tid = threadIdx.x;
    int lane = tid & 31, w = tid >> 5;
    int g = lane >> 2, t = lane & 3;
    int p  = blockIdx.x;
    int hh = p & 7, tq = p >> 3;
    const float cs = 0.08838834764831845f * 1.4426950408889634f; // 1/sqrt(128)*log2e

    if (tid < 64)       wsq[tid]     = ((const float4*)Wq)[tid];
    else if (tid < 128) wsk[tid-64]  = ((const float4*)Wk)[tid-64];
    else if (tid < 192) wsv[tid-128] = ((const float4*)Wv)[tid-128];
    __syncthreads();

    // ---- staging: project 2 nodes/thread, pack fp16 ----
    #pragma unroll
    for (int rr = 0; rr < 2; rr++) {
        int node = tid + rr*256;
        const float4* xin = (const float4*)(values + (node*TT + tq)*CC + hh*DD);
        const float4* yin = (const float4*)(keys   + (node*TT + tq)*CC + hh*DD);
        float4 X[4], Y[4];
        #pragma unroll
        for (int i = 0; i < 4; i++) { X[i] = xin[i]; Y[i] = yin[i]; }
        #pragma unroll
        for (int dp = 0; dp < 8; dp++) {
            float aq0=0.f, ak0=0.f, av0=0.f, aq1=0.f, ak1=0.f, av1=0.f;
            #pragma unroll
            for (int d4 = 0; d4 < 4; d4++) {
                float4 a0 = wsq[(2*dp  )*4 + d4], a1 = wsq[(2*dp+1)*4 + d4];
                aq0 = fmaf(X[d4].x,a0.x,aq0); aq0 = fmaf(X[d4].y,a0.y,aq0);
                aq0 = fmaf(X[d4].z,a0.z,aq0); aq0 = fmaf(X[d4].w,a0.w,aq0);
                aq1 = fmaf(X[d4].x,a1.x,aq1); aq1 = fmaf(X[d4].y,a1.y,aq1);
                aq1 = fmaf(X[d4].z,a1.z,aq1); aq1 = fmaf(X[d4].w,a1.w,aq1);
                float4 b0 = wsk[(2*dp  )*4 + d4], b1 = wsk[(2*dp+1)*4 + d4];
                ak0 = fmaf(Y[d4].x,b0.x,ak0); ak0 = fmaf(Y[d4].y,b0.y,ak0);
                ak0 = fmaf(Y[d4].z,b0.z,ak0); ak0 = fmaf(Y[d4].w,b0.w,ak0);
                ak1 = fmaf(Y[d4].x,b1.x,ak1); ak1 = fmaf(Y[d4].y,b1.y,ak1);
                ak1 = fmaf(Y[d4].z,b1.z,ak1); ak1 = fmaf(Y[d4].w,b1.w,ak1);
                float4 c0 = wsv[(2*dp  )*4 + d4], c1 = wsv[(2*dp+1)*4 + d4];
                av0 = fmaf(X[d4].x,c0.x,av0); av0 = fmaf(X[d4].y,c0.y,av0);
                av0 = fmaf(X[d4].z,c0.z,av0); av0 = fmaf(X[d4].w,c0.w,av0);
                av1 = fmaf(X[d4].x,c1.x,av1); av1 = fmaf(X[d4].y,c1.y,av1);
                av1 = fmaf(X[d4].z,c1.z,av1); av1 = fmaf(X[d4].w,c1.w,av1);
            }
            Qs[node*QSP + dp]   = packh2(aq0*cs, aq1*cs);
            Kth[dp*KTP + node]  = packh2(ak0, ak1);
            Vth[(2*dp  )*528 + node] = __float2half_rn(av0);
            Vth[(2*dp+1)*528 + node] = __float2half_rn(av1);
        }
    }
    __syncthreads();

    // ---- Q fragments: warp rows w*64 .. +63 ----
    uint32_t qa[4][4];
    #pragma unroll
    for (int u = 0; u < 4; u++) {
        int base = w*64 + u*16;
        qa[u][0] = Qs[(base+g  )*QSP + t];
        qa[u][1] = Qs[(base+g+8)*QSP + t];
        qa[u][2] = Qs[(base+g  )*QSP + t + 4];
        qa[u][3] = Qs[(base+g+8)*QSP + t + 4];
    }

    float o[4][8], lc[4][4];
    #pragma unroll
    for (int u = 0; u < 4; u++) {
        #pragma unroll
        for (int i = 0; i < 8; i++) o[u][i] = 0.f;
        #pragma unroll
        for (int i = 0; i < 4; i++) lc[u][i] = 0.f;
    }

    const uint32_t* Vw = (const uint32_t*)Vth;
    const uint32_t ONES = 0x3C003C00u;

    #pragma unroll 2
    for (int tile = 0; tile < 32; tile++) {
        int n0 = tile*16, np0 = tile*8;
        uint32_t kb0 = Kth[(t  )*KTP + n0 + g];
        uint32_t kb1 = Kth[(t+4)*KTP + n0 + g];
        uint32_t kb2 = Kth[(t  )*KTP + n0 + 8 + g];
        uint32_t kb3 = Kth[(t+4)*KTP + n0 + 8 + g];
        uint32_t vb0 = Vw[(g  )*VTPW + np0 + t];
        uint32_t vb1 = Vw[(g  )*VTPW + np0 + t + 4];
        uint32_t vb2 = Vw[(g+8)*VTPW + np0 + t];
        uint32_t vb3 = Vw[(g+8)*VTPW + np0 + t + 4];
        #pragma unroll
        for (int u = 0; u < 4; u++) {
            float f0=0.f,f1=0.f,f2=0.f,f3=0.f;
            float h0=0.f,h1=0.f,h2=0.f,h3=0.f;
            mma_f16(f0,f1,f2,f3, qa[u][0],qa[u][1],qa[u][2],qa[u][3], kb0,kb1);
            mma_f16(h0,h1,h2,h3, qa[u][0],qa[u][1],qa[u][2],qa[u][3], kb2,kb3);
            uint32_t pa0 = ex2h2(packh2(f0,f1));
            uint32_t pa1 = ex2h2(packh2(f2,f3));
            uint32_t pa2 = ex2h2(packh2(h0,h1));
            uint32_t pa3 = ex2h2(packh2(h2,h3));
            mma_f16(o[u][0],o[u][1],o[u][2],o[u][3], pa0,pa1,pa2,pa3, vb0,vb1);
            mma_f16(o[u][4],o[u][5],o[u][6],o[u][7], pa0,pa1,pa2,pa3, vb2,vb3);
            mma_f16(lc[u][0],lc[u][1],lc[u][2],lc[u][3], pa0,pa1,pa2,pa3, ONES,ONES);
        }
    }

    #pragma unroll
    for (int u = 0; u < 4; u++) {
        float ia = 1.0f / lc[u][0];
        float ib = 1.0f / lc[u][2];
        int node = w*64 + u*16 + g;
        uint32_t* d0 = g_O16 + (node*TT + tq)*(HH*8) + hh*8;
        uint32_t* d1 = d0 + 8*TT*(HH*8);   // node+8 (row stride = HH*8 u32)
        d0[t]   = packh2(o[u][0]*ia, o[u][1]*ia);
        d0[t+4] = packh2(o[u][4]*ia, o[u][5]*ia);
        d1[t]   = packh2(o[u][2]*ib, o[u][3]*ib);
        d1[t+4] = packh2(o[u][6]*ib, o[u][7]*ib);
    }
}

// ---------------------------------------------------------------------------
// Kernel 2: final FC, fp16 mma, pre-converted W. 64 rows/CTA, grid 256,
// 2 CTAs/SM (88.5KB smem). Staging = pure coalesced copies. Warp = 16 rows
// x 64 cols. Bank maps: Wh/Wl pitch 136 (8t+g perfect), X pitch 72 (8g+t).
// ---------------------------------------------------------------------------
#define FCWHP 136
#define FCXP 72
#define FC_WH 0
#define FC_WL (64*FCWHP)                      // 8704
#define FC_X  (FC_WL + 64*FCWHP)              // 17408
#define FC_B  (FC_X + 64*FCXP)                // 22016
#define FC_SMEM ((FC_B + CC) * 4)             // 88576 B

__global__ __launch_bounds__(256, 2) void fc_kernel(
    const float* __restrict__ bfc, float* __restrict__ out)
{
    extern __shared__ uint32_t shu[];
    uint32_t* Whs = shu + FC_WH;              // [64 cp][136 e]
    uint32_t* Wls = shu + FC_WL;              // [64 cp][136 e]
    uint32_t* X16 = shu + FC_X;               // [64 r][72 dpair]
    float*    Bs  = (float*)(shu + FC_B);
    int tid = threadIdx.x;
    int lane = tid & 31, w = tid >> 5;
    int g = lane >> 2, t = lane & 3;
    int row0 = blockIdx.x * 64;

    // stage: coalesced copies only (no conversion, no transpose)
    #pragma unroll
    for (int j = 0; j < 8; j++) {
        int i4 = tid + j*256;                 // 2048 float4 per array
        int cp = i4 >> 5, e4 = (i4 & 31) << 2;
        *(float4*)(Whs + cp*FCWHP + e4) = ((const float4*)g_Wh)[i4];
        *(float4*)(Wls + cp*FCWHP + e4) = ((const float4*)g_Wl)[i4];
    }
    #pragma unroll
    for (int j = 0; j < 4; j++) {
        int i4 = tid + j*256;                 // 1024 float4
        int r = i4 >> 4, c4 = (i4 & 15) << 2;
        *(float4*)(X16 + r*FCXP + c4) = *(const float4*)(g_O16 + (row0 + r)*64 + c4);
    }
    if (tid < CC) Bs[tid] = bfc[tid];
    __syncthreads();

    // warp -> rowgroup (w&3)*16, col half (w>>2)*64
    int rg = (w & 3) * 16, eq = (w >> 2) * 64;
    float acc[8][4];
    #pragma unroll
    for (int nt = 0; nt < 8; nt++)
        #pragma unroll
        for (int i = 0; i < 4; i++) acc[nt][i] = 0.f;

    #pragma unroll
    for (int kk = 0; kk < 8; kk++) {
        uint32_t a0 = X16[(rg+g  )*FCXP + kk*8 + t];
        uint32_t a1 = X16[(rg+g+8)*FCXP + kk*8 + t];
        uint32_t a2 = X16[(rg+g  )*FCXP + kk*8 + t + 4];
        uint32_t a3 = X16[(rg+g+8)*FCXP + kk*8 + t + 4];
        #pragma unroll
        for (int nt = 0; nt < 8; nt++) {
            int e0 = eq + nt*8;
            uint32_t bh0 = Whs[(kk*8+t  )*FCWHP + e0 + g];
            uint32_t bh1 = Whs[(kk*8+t+4)*FCWHP + e0 + g];
            uint32_t bl0 = Wls[(kk*8+t  )*FCWHP + e0 + g];
            uint32_t bl1 = Wls[(kk*8+t+4)*FCWHP + e0 + g];
            mma_f16(acc[nt][0],acc[nt][1],acc[nt][2],acc[nt][3], a0,a1,a2,a3, bh0,bh1);
            mma_f16(acc[nt][0],acc[nt][1],acc[nt][2],acc[nt][3], a0,a1,a2,a3, bl0,bl1);
        }
    }

    #pragma unroll
    for (int nt = 0; nt < 8; nt++) {
        int e = eq + nt*8 + 2*t;
        float b0 = Bs[e], b1 = Bs[e+1];
        int R = row0 + rg + g;
        *(float2*)(out + R*CC + e)     = make_float2(acc[nt][0] + b0, acc[nt][1] + b1);
        *(float2*)(out + (R+8)*CC + e) = make_float2(acc[nt][2] + b0, acc[nt][3] + b1);
    }
}

// ---------------------------------------------------------------------------
extern "C" void kernel_launch(void* const* d_in, const int* in_sizes, int n_in,
                              void* d_out, int out_size)
{
    const float *values = nullptr, *keys = nullptr, *query = nullptr;
    const float *Wq = nullptr, *Wk = nullptr, *Wv = nullptr;
    const float *Wfc = nullptr, *bfc = nullptr;
    for (int i = 0; i < n_in; i++) {
        int sz = in_sizes[i];
        const float* ptr = (const float*)d_in[i];
        if (sz == NN*TT*CC) {
            if (!values) values = ptr; else if (!keys) keys = ptr; else if (!query) query = ptr;
        } else if (sz == DD*DD) {
            if (!Wq) Wq = ptr; else if (!Wk) Wk = ptr; else if (!Wv) Wv = ptr;
        } else if (sz == CC*CC) {
            Wfc = ptr;
        } else if (sz == CC) {
            bfc = ptr;
        }
    }

    cudaFuncSetAttribute(fused_attn_kernel, cudaFuncAttributeMaxDynamicSharedMemorySize, ATTN_SMEM);
    cudaFuncSetAttribute(fc_kernel, cudaFuncAttributeMaxDynamicSharedMemorySize, FC_SMEM);

    w16_prep<<<32, 256>>>(Wfc);
    fused_attn_kernel<<<TT*HH, 256, ATTN_SMEM>>>(values, keys, Wq, Wk, Wv);
    fc_kernel<<<(NN*TT)/64, 256, FC_SMEM>>>(bfc, (float*)d_out);
}

// round 9
// speedup vs baseline: 4.4818x; 1.0891x over previous
#include <cuda_runtime.h>
#include <cuda_fp16.h>
#include <cstdint>

#define NN 512          // nodes (attention axis)
#define TT 32           // time steps
#define HH 8            // heads
#define DD 16           // per-head dim
#define CC 128          // embed

// Attention output: [node][t][h][dpair] as half2-in-u32, row-major = [row R][64]
__device__ uint32_t g_O16[NN*TT*HH*8];
// Pre-converted FC weights, B-operand layout [cpair 64][e 128], fp16 pairs
__device__ uint32_t g_Wh[64*CC];

__device__ __forceinline__ uint32_t packh2(float lo, float hi){
    uint32_t r; asm("cvt.rn.f16x2.f32 %0, %1, %2;" : "=r"(r) : "f"(hi), "f"(lo)); return r;
}
__device__ __forceinline__ uint32_t ex2h2(uint32_t x){
    uint32_t r; asm("ex2.approx.f16x2 %0, %1;" : "=r"(r) : "r"(x)); return r;
}
__device__ __forceinline__ uint32_t hadd2(uint32_t a, uint32_t b){
    uint32_t r; asm("add.f16x2 %0, %1, %2;" : "=r"(r) : "r"(a), "r"(b)); return r;
}
__device__ __forceinline__ float h2sum(uint32_t v){
    __half2 h = *(__half2*)&v;
    return __half2float(__low2half(h)) + __half2float(__high2half(h));
}
__device__ __forceinline__ void mma_f16(float& c0, float& c1, float& c2, float& c3,
                                        uint32_t a0, uint32_t a1, uint32_t a2, uint32_t a3,
                                        uint32_t b0, uint32_t b1){
    asm volatile("mma.sync.aligned.m16n8k16.row.col.f32.f16.f16.f32 "
                 "{%0,%1,%2,%3},{%4,%5,%6,%7},{%8,%9},{%0,%1,%2,%3};"
                 : "+f"(c0), "+f"(c1), "+f"(c2), "+f"(c3)
                 : "r"(a0), "r"(a1), "r"(a2), "r"(a3), "r"(b0), "r"(b1));
}

// ---------------------------------------------------------------------------
// Kernel 1: FUSED proj + attention, fp16 m16n8k16.
//  - CTAs 0..31 additionally convert Wfc -> g_Wh (fc reads it next launch).
//  - l accumulated via add.f16x2 partials (no ones-mma): 20% fewer HMMA.
// ---------------------------------------------------------------------------
#define QSP 12
#define KTP 520
#define VTPW 264
#define SM_QS 0
#define SM_KT (512*QSP)                   // u32 index
#define SM_VT (SM_KT + 8*KTP)
#define SM_W  (SM_VT + 16*VTPW)
#define ATTN_SMEM ((SM_W + 3*256) * 4)    // 61184 B

__global__ __launch_bounds__(256, 2) void fused_attn_kernel(
    const float* __restrict__ values, const float* __restrict__ keys,
    const float* __restrict__ Wq, const float* __restrict__ Wk,
    const float* __restrict__ Wv, const float* __restrict__ Wfc)
{
    extern __shared__ uint32_t smu[];
    uint32_t* Qs  = smu + SM_QS;          // [512][12] half2
    uint32_t* Kth = smu + SM_KT;          // [8][520]  half2 (d-pairs)
    __half*   Vth = (__half*)(smu + SM_VT); // [16][528] half
    float4* wsq = (float4*)(smu + SM_W);
    float4* wsk = wsq + 64;
    float4* wsv = wsk + 64;

    int tid = threadIdx.x;
    int lane = tid & 31, w = tid >> 5;
    int g = lane >> 2, t = lane & 3;
    int p  = blockIdx.x;
    int hh = p & 7, tq = p >> 3;
    const float cs = 0.08838834764831845f * 1.4426950408889634f; // 1/sqrt(128)*log2e

    // ---- folded one-shot W16 prep (fc consumes next launch) ----
    if (p < 32) {
        int i = p*256 + tid;              // 0..8191
        int cp = i >> 7, e = i & 127;
        g_Wh[i] = packh2(Wfc[e*CC + 2*cp], Wfc[e*CC + 2*cp + 1]);
    }

    if (tid < 64)       wsq[tid]     = ((const float4*)Wq)[tid];
    else if (tid < 128) wsk[tid-64]  = ((const float4*)Wk)[tid-64];
    else if (tid < 192) wsv[tid-128] = ((const float4*)Wv)[tid-128];
    __syncthreads();

    // ---- staging: project 2 nodes/thread, pack fp16 ----
    #pragma unroll
    for (int rr = 0; rr < 2; rr++) {
        int node = tid + rr*256;
        const float4* xin = (const float4*)(values + (node*TT + tq)*CC + hh*DD);
        const float4* yin = (const float4*)(keys   + (node*TT + tq)*CC + hh*DD);
        float4 X[4], Y[4];
        #pragma unroll
        for (int i = 0; i < 4; i++) { X[i] = xin[i]; Y[i] = yin[i]; }
        #pragma unroll
        for (int dp = 0; dp < 8; dp++) {
            float aq0=0.f, ak0=0.f, av0=0.f, aq1=0.f, ak1=0.f, av1=0.f;
            #pragma unroll
            for (int d4 = 0; d4 < 4; d4++) {
                float4 a0 = wsq[(2*dp  )*4 + d4], a1 = wsq[(2*dp+1)*4 + d4];
                aq0 = fmaf(X[d4].x,a0.x,aq0); aq0 = fmaf(X[d4].y,a0.y,aq0);
                aq0 = fmaf(X[d4].z,a0.z,aq0); aq0 = fmaf(X[d4].w,a0.w,aq0);
                aq1 = fmaf(X[d4].x,a1.x,aq1); aq1 = fmaf(X[d4].y,a1.y,aq1);
                aq1 = fmaf(X[d4].z,a1.z,aq1); aq1 = fmaf(X[d4].w,a1.w,aq1);
                float4 b0 = wsk[(2*dp  )*4 + d4], b1 = wsk[(2*dp+1)*4 + d4];
                ak0 = fmaf(Y[d4].x,b0.x,ak0); ak0 = fmaf(Y[d4].y,b0.y,ak0);
                ak0 = fmaf(Y[d4].z,b0.z,ak0); ak0 = fmaf(Y[d4].w,b0.w,ak0);
                ak1 = fmaf(Y[d4].x,b1.x,ak1); ak1 = fmaf(Y[d4].y,b1.y,ak1);
                ak1 = fmaf(Y[d4].z,b1.z,ak1); ak1 = fmaf(Y[d4].w,b1.w,ak1);
                float4 c0 = wsv[(2*dp  )*4 + d4], c1 = wsv[(2*dp+1)*4 + d4];
                av0 = fmaf(X[d4].x,c0.x,av0); av0 = fmaf(X[d4].y,c0.y,av0);
                av0 = fmaf(X[d4].z,c0.z,av0); av0 = fmaf(X[d4].w,c0.w,av0);
                av1 = fmaf(X[d4].x,c1.x,av1); av1 = fmaf(X[d4].y,c1.y,av1);
                av1 = fmaf(X[d4].z,c1.z,av1); av1 = fmaf(X[d4].w,c1.w,av1);
            }
            Qs[node*QSP + dp]   = packh2(aq0*cs, aq1*cs);
            Kth[dp*KTP + node]  = packh2(ak0, ak1);
            Vth[(2*dp  )*528 + node] = __float2half_rn(av0);
            Vth[(2*dp+1)*528 + node] = __float2half_rn(av1);
        }
    }
    __syncthreads();

    // ---- Q fragments: warp rows w*64 .. +63 ----
    uint32_t qa[4][4];
    #pragma unroll
    for (int u = 0; u < 4; u++) {
        int base = w*64 + u*16;
        qa[u][0] = Qs[(base+g  )*QSP + t];
        qa[u][1] = Qs[(base+g+8)*QSP + t];
        qa[u][2] = Qs[(base+g  )*QSP + t + 4];
        qa[u][3] = Qs[(base+g+8)*QSP + t + 4];
    }

    float o[4][8];
    uint32_t lacc[4][2];
    #pragma unroll
    for (int u = 0; u < 4; u++) {
        #pragma unroll
        for (int i = 0; i < 8; i++) o[u][i] = 0.f;
        lacc[u][0] = 0u; lacc[u][1] = 0u;
    }

    const uint32_t* Vw = (const uint32_t*)Vth;

    #pragma unroll 2
    for (int tile = 0; tile < 32; tile++) {
        int n0 = tile*16, np0 = tile*8;
        uint32_t kb0 = Kth[(t  )*KTP + n0 + g];
        uint32_t kb1 = Kth[(t+4)*KTP + n0 + g];
        uint32_t kb2 = Kth[(t  )*KTP + n0 + 8 + g];
        uint32_t kb3 = Kth[(t+4)*KTP + n0 + 8 + g];
        uint32_t vb0 = Vw[(g  )*VTPW + np0 + t];
        uint32_t vb1 = Vw[(g  )*VTPW + np0 + t + 4];
        uint32_t vb2 = Vw[(g+8)*VTPW + np0 + t];
        uint32_t vb3 = Vw[(g+8)*VTPW + np0 + t + 4];
        #pragma unroll
        for (int u = 0; u < 4; u++) {
            float f0=0.f,f1=0.f,f2=0.f,f3=0.f;
            float h0=0.f,h1=0.f,h2=0.f,h3=0.f;
            mma_f16(f0,f1,f2,f3, qa[u][0],qa[u][1],qa[u][2],qa[u][3], kb0,kb1);
            mma_f16(h0,h1,h2,h3, qa[u][0],qa[u][1],qa[u][2],qa[u][3], kb2,kb3);
            uint32_t pa0 = ex2h2(packh2(f0,f1));   // row g,   nodes n0+2t,2t+1
            uint32_t pa1 = ex2h2(packh2(f2,f3));   // row g+8
            uint32_t pa2 = ex2h2(packh2(h0,h1));   // row g,   nodes n0+8+2t,..
            uint32_t pa3 = ex2h2(packh2(h2,h3));   // row g+8
            lacc[u][0] = hadd2(lacc[u][0], hadd2(pa0, pa2));
            lacc[u][1] = hadd2(lacc[u][1], hadd2(pa1, pa3));
            mma_f16(o[u][0],o[u][1],o[u][2],o[u][3], pa0,pa1,pa2,pa3, vb0,vb1);
            mma_f16(o[u][4],o[u][5],o[u][6],o[u][7], pa0,pa1,pa2,pa3, vb2,vb3);
        }
    }

    // ---- epilogue: fp32 quad-combine of fp16 partials, normalize, store ----
    #pragma unroll
    for (int u = 0; u < 4; u++) {
        float la = h2sum(lacc[u][0]);
        float lb = h2sum(lacc[u][1]);
        la += __shfl_xor_sync(0xffffffffu, la, 1);
        la += __shfl_xor_sync(0xffffffffu, la, 2);
        lb += __shfl_xor_sync(0xffffffffu, lb, 1);
        lb += __shfl_xor_sync(0xffffffffu, lb, 2);
        float ia = 1.0f / la, ib = 1.0f / lb;
        int node = w*64 + u*16 + g;
        uint32_t* d0 = g_O16 + (node*TT + tq)*(HH*8) + hh*8;
        uint32_t* d1 = d0 + 8*TT*(HH*8);   // node+8 (row stride = HH*8 u32)
        d0[t]   = packh2(o[u][0]*ia, o[u][1]*ia);
        d0[t+4] = packh2(o[u][4]*ia, o[u][5]*ia);
        d1[t]   = packh2(o[u][2]*ib, o[u][3]*ib);
        d1[t+4] = packh2(o[u][6]*ib, o[u][7]*ib);
    }
}

// ---------------------------------------------------------------------------
// Kernel 2: final FC, fp16 mma, single pre-converted W. 64 rows/CTA, grid 256,
// 3 CTAs/SM (54KB smem). Staging = pure coalesced copies.
// ---------------------------------------------------------------------------
#define FCWHP 136
#define FCXP 72
#define FC_WH 0
#define FC_X  (64*FCWHP)                      // 8704
#define FC_B  (FC_X + 64*FCXP)                // 13312
#define FC_SMEM ((FC_B + CC) * 4)             // 53760 B

__global__ __launch_bounds__(256, 3) void fc_kernel(
    const float* __restrict__ bfc, float* __restrict__ out)
{
    extern __shared__ uint32_t shu[];
    uint32_t* Whs = shu + FC_WH;              // [64 cp][136 e]
    uint32_t* X16 = shu + FC_X;               // [64 r][72 dpair]
    float*    Bs  = (float*)(shu + FC_B);
    int tid = threadIdx.x;
    int lane = tid & 31, w = tid >> 5;
    int g = lane >> 2, t = lane & 3;
    int row0 = blockIdx.x * 64;

    #pragma unroll
    for (int j = 0; j < 8; j++) {
        int i4 = tid + j*256;                 // 2048 float4
        int cp = i4 >> 5, e4 = (i4 & 31) << 2;
        *(float4*)(Whs + cp*FCWHP + e4) = ((const float4*)g_Wh)[i4];
    }
    #pragma unroll
    for (int j = 0; j < 4; j++) {
        int i4 = tid + j*256;                 // 1024 float4
        int r = i4 >> 4, c4 = (i4 & 15) << 2;
        *(float4*)(X16 + r*FCXP + c4) = *(const float4*)(g_O16 + (row0 + r)*64 + c4);
    }
    if (tid < CC) Bs[tid] = bfc[tid];
    __syncthreads();

    int rg = (w & 3) * 16, eq = (w >> 2) * 64;
    float acc[8][4];
    #pragma unroll
    for (int nt = 0; nt < 8; nt++)
        #pragma unroll
        for (int i = 0; i < 4; i++) acc[nt][i] = 0.f;

    #pragma unroll
    for (int kk = 0; kk < 8; kk++) {
        uint32_t a0 = X16[(rg+g  )*FCXP + kk*8 + t];
        uint32_t a1 = X16[(rg+g+8)*FCXP + kk*8 + t];
        uint32_t a2 = X16[(rg+g  )*FCXP + kk*8 + t + 4];
        uint32_t a3 = X16[(rg+g+8)*FCXP + kk*8 + t + 4];
        #pragma unroll
        for (int nt = 0; nt < 8; nt++) {
            int e0 = eq + nt*8;
            uint32_t bh0 = Whs[(kk*8+t  )*FCWHP + e0 + g];
            uint32_t bh1 = Whs[(kk*8+t+4)*FCWHP + e0 + g];
            mma_f16(acc[nt][0],acc[nt][1],acc[nt][2],acc[nt][3], a0,a1,a2,a3, bh0,bh1);
        }
    }

    #pragma unroll
    for (int nt = 0; nt < 8; nt++) {
        int e = eq + nt*8 + 2*t;
        float b0 = Bs[e], b1 = Bs[e+1];
        int R = row0 + rg + g;
        *(float2*)(out + R*CC + e)     = make_float2(acc[nt][0] + b0, acc[nt][1] + b1);
        *(float2*)(out + (R+8)*CC + e) = make_float2(acc[nt][2] + b0, acc[nt][3] + b1);
    }
}

// ---------------------------------------------------------------------------
extern "C" void kernel_launch(void* const* d_in, const int* in_sizes, int n_in,
                              void* d_out, int out_size)
{
    const float *values = nullptr, *keys = nullptr, *query = nullptr;
    const float *Wq = nullptr, *Wk = nullptr, *Wv = nullptr;
    const float *Wfc = nullptr, *bfc = nullptr;
    for (int i = 0; i < n_in; i++) {
        int sz = in_sizes[i];
        const float* ptr = (const float*)d_in[i];
        if (sz == NN*TT*CC) {
            if (!values) values = ptr; else if (!keys) keys = ptr; else if (!query) query = ptr;
        } else if (sz == DD*DD) {
            if (!Wq) Wq = ptr; else if (!Wk) Wk = ptr; else if (!Wv) Wv = ptr;
        } else if (sz == CC*CC) {
            Wfc = ptr;
        } else if (sz == CC) {
            bfc = ptr;
        }
    }

    cudaFuncSetAttribute(fused_attn_kernel, cudaFuncAttributeMaxDynamicSharedMemorySize, ATTN_SMEM);
    cudaFuncSetAttribute(fc_kernel, cudaFuncAttributeMaxDynamicSharedMemorySize, FC_SMEM);

    fused_attn_kernel<<<TT*HH, 256, ATTN_SMEM>>>(values, keys, Wq, Wk, Wv, Wfc);
    fc_kernel<<<(NN*TT)/64, 256, FC_SMEM>>>(bfc, (float*)d_out);
}